// round 1
// baseline (speedup 1.0000x reference)
#include <cuda_runtime.h>

#define NN 50000
#define NE 1280000
#define NG 64
#define H  64
#define NEG_BITS 0xFF800000u

// Scratch (device globals; no allocation allowed)
__device__ float g_h1[NN * H];
__device__ float g_h2[NN * H];
__device__ float g_gf[NG * 2 * H];

__device__ __forceinline__ float lrelu(float x) { return fmaxf(x, 0.2f * x); }

// float atomic max via sign-split int atomics (REDG, no return).
// -0.0f canonicalized to +0.0f so float ordering is preserved.
__device__ __forceinline__ void atomMaxF(float* a, float v) {
    int bi = __float_as_int(v);
    if (bi == (int)0x80000000) bi = 0;
    if (bi >= 0) atomicMax((int*)a, bi);
    else         atomicMin((unsigned int*)a, (unsigned int)bi);
}

__global__ void init_kernel() {
    int i = blockIdx.x * blockDim.x + threadIdx.x;
    if (i < NN * H) {
        float ni = __int_as_float((int)NEG_BITS);
        g_h1[i] = ni;
        g_h2[i] = ni;
    }
}

template <int WHICH>
__global__ void fix_kernel() {
    int i = blockIdx.x * blockDim.x + threadIdx.x;
    if (i < NN * H) {
        float* a = (WHICH == 1) ? g_h1 : g_h2;
        if (__float_as_int(a[i]) == (int)NEG_BITS) a[i] = 0.0f;
    }
}

// Accumulate one input-dim j into all 64 hidden accumulators:
// t[k] += xi * Wa[j][k] + (xj - xi) * Wa[FIN + j][k]
__device__ __forceinline__ void accum_row(float t[H], const float* r0, const float* r1,
                                          float xi, float dj) {
    const float4* R0 = (const float4*)r0;
    const float4* R1 = (const float4*)r1;
#pragma unroll
    for (int q = 0; q < 16; q++) {
        float4 w0 = R0[q];
        float4 w1 = R1[q];
        t[4 * q + 0] = fmaf(xi, w0.x, fmaf(dj, w1.x, t[4 * q + 0]));
        t[4 * q + 1] = fmaf(xi, w0.y, fmaf(dj, w1.y, t[4 * q + 1]));
        t[4 * q + 2] = fmaf(xi, w0.z, fmaf(dj, w1.z, t[4 * q + 2]));
        t[4 * q + 3] = fmaf(xi, w0.w, fmaf(dj, w1.w, t[4 * q + 3]));
    }
}

// One thread per edge. FIN = per-node input feature count (6 or 64).
// Layer1: t = lrelu([xi, xj-xi] @ Wa + ba)   (Wa natural layout [2*FIN][64] in smem)
// Layer2: out = lrelu(t @ Wb + bb)           (Wb transposed [64][64] in smem)
// Aggregation: atomic float-max onto agg[dst].
template <int FIN>
__global__ __launch_bounds__(128)
void edgeconv_kernel(const float* __restrict__ xext,
                     const int* __restrict__ src, const int* __restrict__ dst,
                     const float* __restrict__ Wa, const float* __restrict__ ba,
                     const float* __restrict__ Wb, const float* __restrict__ bb) {
    __shared__ float sWa[2 * FIN * 64];
    __shared__ float sWbT[64 * 64];

    const float* xin = (FIN == 6) ? xext : (const float*)g_h1;
    float* agg = (FIN == 6) ? g_h1 : g_h2;

    int tid = threadIdx.x;
    for (int i = tid; i < 2 * FIN * 64; i += 128) sWa[i] = Wa[i];
    for (int i = tid; i < 64 * 64; i += 128) {
        int k = i >> 6, k2 = i & 63;
        sWbT[k2 * 64 + k] = Wb[i];
    }
    __syncthreads();

    int e = blockIdx.x * 128 + tid;
    if (e >= NE) return;
    int s = src[e], d = dst[e];
    const float* xs = xin + (size_t)s * FIN;
    const float* xd = xin + (size_t)d * FIN;

    float t[H];
#pragma unroll
    for (int q = 0; q < 16; q++) {
        float4 b4 = __ldg((const float4*)ba + q);
        t[4 * q + 0] = b4.x; t[4 * q + 1] = b4.y;
        t[4 * q + 2] = b4.z; t[4 * q + 3] = b4.w;
    }

    // Layer 1 (input dims streamed as float2 chunks; weight rows broadcast from smem)
#pragma unroll 1
    for (int jc = 0; jc < FIN / 2; jc++) {
        float2 xi2 = ((const float2*)xd)[jc];
        float2 xj2 = ((const float2*)xs)[jc];
        int j0 = 2 * jc;
        accum_row(t, sWa + (size_t)j0 * 64,       sWa + (size_t)(FIN + j0) * 64,
                  xi2.x, xj2.x - xi2.x);
        accum_row(t, sWa + (size_t)(j0 + 1) * 64, sWa + (size_t)(FIN + j0 + 1) * 64,
                  xi2.y, xj2.y - xi2.y);
    }
#pragma unroll
    for (int k = 0; k < H; k++) t[k] = lrelu(t[k]);

    // Layer 2 + atomic max aggregation onto dst
    float* aggd = agg + (size_t)d * H;
#pragma unroll 1
    for (int k2 = 0; k2 < 64; k2++) {
        float acc = __ldg(bb + k2);
        const float4* wr = (const float4*)(sWbT + k2 * 64);
#pragma unroll
        for (int q = 0; q < 16; q++) {
            float4 w = wr[q];
            acc = fmaf(t[4 * q + 0], w.x, acc);
            acc = fmaf(t[4 * q + 1], w.y, acc);
            acc = fmaf(t[4 * q + 2], w.z, acc);
            acc = fmaf(t[4 * q + 3], w.w, acc);
        }
        atomMaxF(aggd + k2, lrelu(acc));
    }
}

// One block per graph: binary-search node range in sorted batch, mean+max pool h2.
__global__ void pool_kernel(const int* __restrict__ batch) {
    int g = blockIdx.x;
    int lo = 0, hi = NN;
    while (lo < hi) { int m = (lo + hi) >> 1; if (batch[m] < g) lo = m + 1; else hi = m; }
    int start = lo;
    hi = NN;
    while (lo < hi) { int m = (lo + hi) >> 1; if (batch[m] <= g) lo = m + 1; else hi = m; }
    int end = lo;

    int tid = threadIdx.x;
    int k = tid & 63, grp = tid >> 6;
    float s = 0.f;
    float mx = __int_as_float((int)NEG_BITS);
    for (int n = start + grp; n < end; n += 4) {
        float v = g_h2[(size_t)n * H + k];
        s += v;
        mx = fmaxf(mx, v);
    }
    __shared__ float ss[256], sm[256];
    ss[tid] = s; sm[tid] = mx;
    __syncthreads();
    if (grp == 0) {
        s += ss[64 + k] + ss[128 + k] + ss[192 + k];
        mx = fmaxf(fmaxf(mx, sm[64 + k]), fmaxf(sm[128 + k], sm[192 + k]));
        float cnt = (float)((end - start) > 1 ? (end - start) : 1);
        g_gf[g * 128 + k] = s / cnt;
        g_gf[g * 128 + 64 + k] = (__float_as_int(mx) == (int)NEG_BITS) ? 0.f : mx;
    }
}

// 64 blocks (one per graph) x 64 threads: logits = lrelu(g @ Wc1 + bc1) @ Wc2 + bc2
__global__ void cls_kernel(const float* __restrict__ Wc1, const float* __restrict__ bc1,
                           const float* __restrict__ Wc2, const float* __restrict__ bc2,
                           float* __restrict__ out) {
    int g = blockIdx.x, t = threadIdx.x;
    __shared__ float gv[128];
    gv[t] = g_gf[g * 128 + t];
    gv[t + 64] = g_gf[g * 128 + 64 + t];
    __syncthreads();
    float acc = __ldg(bc1 + t);
#pragma unroll 8
    for (int j = 0; j < 128; j++) acc = fmaf(gv[j], Wc1[j * 64 + t], acc);
    float v = lrelu(acc) * __ldg(Wc2 + t);
#pragma unroll
    for (int o = 16; o > 0; o >>= 1) v += __shfl_down_sync(0xffffffffu, v, o);
    __shared__ float part[2];
    if ((t & 31) == 0) part[t >> 5] = v;
    __syncthreads();
    if (t == 0) out[g] = part[0] + part[1] + __ldg(bc2);
}

extern "C" void kernel_launch(void* const* d_in, const int* in_sizes, int n_in,
                              void* d_out, int out_size) {
    const float* x    = (const float*)d_in[0];
    const int*   ei   = (const int*)d_in[1];
    const int*   batch= (const int*)d_in[2];
    const float* W1   = (const float*)d_in[3];
    const float* b1   = (const float*)d_in[4];
    const float* W2   = (const float*)d_in[5];
    const float* b2   = (const float*)d_in[6];
    const float* W3   = (const float*)d_in[7];
    const float* b3   = (const float*)d_in[8];
    const float* W4   = (const float*)d_in[9];
    const float* b4   = (const float*)d_in[10];
    const float* Wc1  = (const float*)d_in[11];
    const float* bc1  = (const float*)d_in[12];
    const float* Wc2  = (const float*)d_in[13];
    const float* bc2  = (const float*)d_in[14];
    float* out = (float*)d_out;

    const int* src = ei;
    const int* dst = ei + NE;

    init_kernel<<<(NN * H + 255) / 256, 256>>>();
    edgeconv_kernel<6><<<NE / 128, 128>>>(x, src, dst, W1, b1, W2, b2);
    fix_kernel<1><<<(NN * H + 255) / 256, 256>>>();
    edgeconv_kernel<64><<<NE / 128, 128>>>(x, src, dst, W3, b3, W4, b4);
    fix_kernel<2><<<(NN * H + 255) / 256, 256>>>();
    pool_kernel<<<NG, 256>>>(batch);
    cls_kernel<<<NG, 64>>>(Wc1, bc1, Wc2, bc2, out);
}

// round 2
// speedup vs baseline: 1.3230x; 1.3230x over previous
#include <cuda_runtime.h>

#define NN 50000
#define NE 1280000
#define NG 64
#define H  64
#define NEG_BITS 0xFF800000u

// Scratch (device globals; allocation forbidden)
__device__ float g_h1[NN * H];   // conv1 aggregate
__device__ float g_h2[NN * H];   // conv2 aggregate
__device__ float g_P[NN * H];    // per-node P = x@(Wa-Wb)+b
__device__ float g_Q[NN * H];    // per-node Q = x@Wb
__device__ float g_gf[NG * 2 * H];

__device__ __forceinline__ float lrelu(float x) { return fmaxf(x, 0.2f * x); }

// float atomic max via sign-split int atomics (REDG, no return).
__device__ __forceinline__ void atomMaxF(float* a, float v) {
    int bi = __float_as_int(v);
    if (bi == (int)0x80000000) bi = 0;   // canonicalize -0
    if (bi >= 0) atomicMax((int*)a, bi);
    else         atomicMin((unsigned int*)a, (unsigned int)bi);
}

__global__ void init_kernel() {
    int i = blockIdx.x * blockDim.x + threadIdx.x;
    float ni = __int_as_float((int)NEG_BITS);
    float4 v = make_float4(ni, ni, ni, ni);
    if (i < NN * H / 4) {
        ((float4*)g_h1)[i] = v;
        ((float4*)g_h2)[i] = v;
    }
}

// Per-node P,Q for conv1 (FIN=6). One thread per node, computes both.
__global__ __launch_bounds__(128)
void node_mlp6(const float* __restrict__ x, const float* __restrict__ W,
               const float* __restrict__ b) {
    __shared__ float sWd[6 * 64];   // Wa - Wb
    __shared__ float sWq[6 * 64];   // Wb
    int tid = threadIdx.x;
    for (int i = tid; i < 6 * 64; i += 128) {
        float wb = W[6 * 64 + i];
        sWd[i] = W[i] - wb;
        sWq[i] = wb;
    }
    __syncthreads();

    int n = blockIdx.x * 128 + tid;
    if (n >= NN) return;
    float xr[6];
#pragma unroll
    for (int j = 0; j < 6; j++) xr[j] = x[(size_t)n * 6 + j];

    float* Pp = g_P + (size_t)n * 64;
    float* Qp = g_Q + (size_t)n * 64;
#pragma unroll 4
    for (int k = 0; k < 64; k++) {
        float p = __ldg(b + k), q = 0.f;
#pragma unroll
        for (int j = 0; j < 6; j++) {
            p = fmaf(xr[j], sWd[j * 64 + k], p);
            q = fmaf(xr[j], sWq[j * 64 + k], q);
        }
        Pp[k] = p;
        Qp[k] = q;
    }
}

// Per-node P (blockIdx.y==0) or Q (blockIdx.y==1) for conv2 (FIN=64).
// Reads g_h1 with inline neg-inf -> 0 fix.
__global__ __launch_bounds__(128)
void node_mlp64(const float* __restrict__ W, const float* __restrict__ b) {
    __shared__ float sWT[64 * 64];  // transposed: sWT[k][j]
    int tid = threadIdx.x;
    bool isP = (blockIdx.y == 0);
    for (int i = tid; i < 4096; i += 128) {
        int j = i >> 6, k = i & 63;
        float wb = W[(64 + j) * 64 + k];
        sWT[k * 64 + j] = isP ? (W[i] - wb) : wb;
    }
    __syncthreads();

    int n = blockIdx.x * 128 + tid;
    if (n >= NN) return;

    float t[64];
    const float4* hr = (const float4*)(g_h1 + (size_t)n * 64);
#pragma unroll
    for (int q = 0; q < 16; q++) {
        float4 v = hr[q];
        t[4 * q + 0] = (__float_as_int(v.x) == (int)NEG_BITS) ? 0.f : v.x;
        t[4 * q + 1] = (__float_as_int(v.y) == (int)NEG_BITS) ? 0.f : v.y;
        t[4 * q + 2] = (__float_as_int(v.z) == (int)NEG_BITS) ? 0.f : v.z;
        t[4 * q + 3] = (__float_as_int(v.w) == (int)NEG_BITS) ? 0.f : v.w;
    }

    float* outp = (isP ? g_P : g_Q) + (size_t)n * 64;
#pragma unroll 1
    for (int k0 = 0; k0 < 64; k0 += 4) {
        float4 ov;
        float* po = &ov.x;
#pragma unroll
        for (int kk = 0; kk < 4; kk++) {
            int k = k0 + kk;
            float a0 = isP ? __ldg(b + k) : 0.f, a1 = 0.f, a2 = 0.f, a3 = 0.f;
            const float4* wr = (const float4*)(sWT + k * 64);
#pragma unroll
            for (int q = 0; q < 16; q += 4) {
                float4 w0 = wr[q], w1 = wr[q + 1], w2 = wr[q + 2], w3 = wr[q + 3];
                a0 = fmaf(t[4*q+0],  w0.x, fmaf(t[4*q+1],  w0.y, fmaf(t[4*q+2],  w0.z, fmaf(t[4*q+3],  w0.w, a0))));
                a1 = fmaf(t[4*q+4],  w1.x, fmaf(t[4*q+5],  w1.y, fmaf(t[4*q+6],  w1.z, fmaf(t[4*q+7],  w1.w, a1))));
                a2 = fmaf(t[4*q+8],  w2.x, fmaf(t[4*q+9],  w2.y, fmaf(t[4*q+10], w2.z, fmaf(t[4*q+11], w2.w, a2))));
                a3 = fmaf(t[4*q+12], w3.x, fmaf(t[4*q+13], w3.y, fmaf(t[4*q+14], w3.z, fmaf(t[4*q+15], w3.w, a3))));
            }
            po[kk] = (a0 + a1) + (a2 + a3);
        }
        ((float4*)outp)[k0 >> 2] = ov;
    }
}

// Fused edge kernel: t = lrelu(P[dst]+Q[src]); out = lrelu(t@Wb+bb); atomic max -> agg[dst].
// PASS selects the aggregate buffer (1 -> g_h1, 2 -> g_h2).
template <int PASS>
__global__ __launch_bounds__(128)
void edge_kernel(const int* __restrict__ src, const int* __restrict__ dst,
                 const float* __restrict__ Wb, const float* __restrict__ bb) {
    __shared__ float sWbT[64 * 64];
    int tid = threadIdx.x;
    for (int i = tid; i < 4096; i += 128) {
        int j = i >> 6, k = i & 63;
        sWbT[k * 64 + j] = Wb[i];
    }
    __syncthreads();

    int e = blockIdx.x * 128 + tid;
    if (e >= NE) return;
    int s = src[e], d = dst[e];

    const float4* Pp = (const float4*)(g_P + (size_t)d * 64);
    const float4* Qp = (const float4*)(g_Q + (size_t)s * 64);
    float t[64];
#pragma unroll
    for (int q = 0; q < 16; q++) {
        float4 a = Pp[q];
        float4 c = Qp[q];
        t[4 * q + 0] = lrelu(a.x + c.x);
        t[4 * q + 1] = lrelu(a.y + c.y);
        t[4 * q + 2] = lrelu(a.z + c.z);
        t[4 * q + 3] = lrelu(a.w + c.w);
    }

    float* agg = (PASS == 1) ? g_h1 : g_h2;
    float* aggd = agg + (size_t)d * 64;
#pragma unroll 1
    for (int k2 = 0; k2 < 64; k2++) {
        float a0 = __ldg(bb + k2), a1 = 0.f, a2 = 0.f, a3 = 0.f;
        const float4* wr = (const float4*)(sWbT + k2 * 64);
#pragma unroll
        for (int q = 0; q < 16; q += 4) {
            float4 w0 = wr[q], w1 = wr[q + 1], w2 = wr[q + 2], w3 = wr[q + 3];
            a0 = fmaf(t[4*q+0],  w0.x, fmaf(t[4*q+1],  w0.y, fmaf(t[4*q+2],  w0.z, fmaf(t[4*q+3],  w0.w, a0))));
            a1 = fmaf(t[4*q+4],  w1.x, fmaf(t[4*q+5],  w1.y, fmaf(t[4*q+6],  w1.z, fmaf(t[4*q+7],  w1.w, a1))));
            a2 = fmaf(t[4*q+8],  w2.x, fmaf(t[4*q+9],  w2.y, fmaf(t[4*q+10], w2.z, fmaf(t[4*q+11], w2.w, a2))));
            a3 = fmaf(t[4*q+12], w3.x, fmaf(t[4*q+13], w3.y, fmaf(t[4*q+14], w3.z, fmaf(t[4*q+15], w3.w, a3))));
        }
        atomMaxF(aggd + k2, lrelu((a0 + a1) + (a2 + a3)));
    }
}

// One block per graph: binary-search node range in sorted batch, mean+max pool g_h2
// with inline neg-inf -> 0 per-node fix (matches reference semantics).
__global__ void pool_kernel(const int* __restrict__ batch) {
    int g = blockIdx.x;
    int lo = 0, hi = NN;
    while (lo < hi) { int m = (lo + hi) >> 1; if (batch[m] < g) lo = m + 1; else hi = m; }
    int start = lo;
    hi = NN;
    while (lo < hi) { int m = (lo + hi) >> 1; if (batch[m] <= g) lo = m + 1; else hi = m; }
    int end = lo;

    int tid = threadIdx.x;
    int k = tid & 63, grp = tid >> 6;
    float s = 0.f;
    float mx = __int_as_float((int)NEG_BITS);
    for (int n = start + grp; n < end; n += 4) {
        float v = g_h2[(size_t)n * H + k];
        v = (__float_as_int(v) == (int)NEG_BITS) ? 0.f : v;
        s += v;
        mx = fmaxf(mx, v);
    }
    __shared__ float ss[256], sm[256];
    ss[tid] = s; sm[tid] = mx;
    __syncthreads();
    if (grp == 0) {
        s += ss[64 + k] + ss[128 + k] + ss[192 + k];
        mx = fmaxf(fmaxf(mx, sm[64 + k]), fmaxf(sm[128 + k], sm[192 + k]));
        float cnt = (float)((end - start) > 1 ? (end - start) : 1);
        g_gf[g * 128 + k] = s / cnt;
        g_gf[g * 128 + 64 + k] = (__float_as_int(mx) == (int)NEG_BITS) ? 0.f : mx;
    }
}

// 64 blocks x 64 threads: logits = lrelu(g @ Wc1 + bc1) @ Wc2 + bc2
__global__ void cls_kernel(const float* __restrict__ Wc1, const float* __restrict__ bc1,
                           const float* __restrict__ Wc2, const float* __restrict__ bc2,
                           float* __restrict__ out) {
    int g = blockIdx.x, t = threadIdx.x;
    __shared__ float gv[128];
    gv[t] = g_gf[g * 128 + t];
    gv[t + 64] = g_gf[g * 128 + 64 + t];
    __syncthreads();
    float acc = __ldg(bc1 + t);
#pragma unroll 8
    for (int j = 0; j < 128; j++) acc = fmaf(gv[j], Wc1[j * 64 + t], acc);
    float v = lrelu(acc) * __ldg(Wc2 + t);
#pragma unroll
    for (int o = 16; o > 0; o >>= 1) v += __shfl_down_sync(0xffffffffu, v, o);
    __shared__ float part[2];
    if ((t & 31) == 0) part[t >> 5] = v;
    __syncthreads();
    if (t == 0) out[g] = part[0] + part[1] + __ldg(bc2);
}

extern "C" void kernel_launch(void* const* d_in, const int* in_sizes, int n_in,
                              void* d_out, int out_size) {
    const float* x    = (const float*)d_in[0];
    const int*   ei   = (const int*)d_in[1];
    const int*   batch= (const int*)d_in[2];
    const float* W1   = (const float*)d_in[3];
    const float* b1   = (const float*)d_in[4];
    const float* W2   = (const float*)d_in[5];
    const float* b2   = (const float*)d_in[6];
    const float* W3   = (const float*)d_in[7];
    const float* b3   = (const float*)d_in[8];
    const float* W4   = (const float*)d_in[9];
    const float* b4   = (const float*)d_in[10];
    const float* Wc1  = (const float*)d_in[11];
    const float* bc1  = (const float*)d_in[12];
    const float* Wc2  = (const float*)d_in[13];
    const float* bc2  = (const float*)d_in[14];
    float* out = (float*)d_out;

    const int* src = ei;
    const int* dst = ei + NE;

    init_kernel<<<(NN * H / 4 + 255) / 256, 256>>>();
    node_mlp6<<<(NN + 127) / 128, 128>>>(x, W1, b1);
    edge_kernel<1><<<NE / 128, 128>>>(src, dst, W2, b2);
    node_mlp64<<<dim3((NN + 127) / 128, 2), 128>>>(W3, b3);
    edge_kernel<2><<<NE / 128, 128>>>(src, dst, W4, b4);
    pool_kernel<<<NG, 256>>>(batch);
    cls_kernel<<<NG, 64>>>(Wc1, bc1, Wc2, bc2, out);
}

// round 3
// speedup vs baseline: 1.6866x; 1.2749x over previous
#include <cuda_runtime.h>

#define NN 50000
#define NE 1280000
#define NG 64
#define H  64
#define NEG_BITS 0xFF800000u

// Scratch (device globals; allocation forbidden)
__device__ float g_h1[NN * H];   // conv1 aggregate (pre-activation max)
__device__ float g_h2[NN * H];   // conv2 aggregate (pre-activation max)
__device__ float g_P[NN * H];    // per-node P = x@(Wa-Wb)+b
__device__ float g_Q[NN * H];    // per-node Q = x@Wb
__device__ float g_gf[NG * 2 * H];
__device__ int   g_cnt[NN + 1];  // histogram
__device__ int   g_off[NN + 1];  // exclusive offsets (consumed by scatter)
__device__ int   g_esrc[NE];     // src, sorted by dst
__device__ int   g_edst[NE];     // dst, sorted

__device__ __forceinline__ float lrelu(float x) { return fmaxf(x, 0.2f * x); }

// float atomic max via sign-split int atomics (REDG, no return).
__device__ __forceinline__ void atomMaxF(float* a, float v) {
    int bi = __float_as_int(v);
    if (bi == (int)0x80000000) bi = 0;   // canonicalize -0
    if (bi >= 0) atomicMax((int*)a, bi);
    else         atomicMin((unsigned int*)a, (unsigned int)bi);
}

// Apply deferred lrelu + neg-inf->0 fix when reading an aggregate value.
__device__ __forceinline__ float fix_act(float v) {
    if (__float_as_int(v) == (int)NEG_BITS) return 0.f;
    return lrelu(v);
}

__global__ void init_kernel() {
    int i = blockIdx.x * blockDim.x + threadIdx.x;
    float ni = __int_as_float((int)NEG_BITS);
    float4 v = make_float4(ni, ni, ni, ni);
    if (i < NN * H / 4) {
        ((float4*)g_h1)[i] = v;
        ((float4*)g_h2)[i] = v;
    }
    if (i <= NN) g_cnt[i] = 0;
}

__global__ void hist_kernel(const int* __restrict__ dst) {
    int e = blockIdx.x * blockDim.x + threadIdx.x;
    if (e < NE) atomicAdd(&g_cnt[dst[e]], 1);
}

// Single-block exclusive scan of g_cnt[0..NN) into g_off.
__global__ void scan_kernel() {
    __shared__ int sums[1024];
    const int CH = (NN + 1023) / 1024;   // 49
    int tid = threadIdx.x;
    int base = tid * CH;
    int s = 0;
    for (int i = 0; i < CH; i++) {
        int idx = base + i;
        if (idx < NN) s += g_cnt[idx];
    }
    sums[tid] = s;
    __syncthreads();
    for (int off = 1; off < 1024; off <<= 1) {
        int v = (tid >= off) ? sums[tid - off] : 0;
        __syncthreads();
        sums[tid] += v;
        __syncthreads();
    }
    int run = (tid == 0) ? 0 : sums[tid - 1];
    for (int i = 0; i < CH; i++) {
        int idx = base + i;
        if (idx < NN) {
            int c = g_cnt[idx];
            g_off[idx] = run;
            run += c;
        }
    }
}

__global__ void scatter_kernel(const int* __restrict__ src, const int* __restrict__ dst) {
    int e = blockIdx.x * blockDim.x + threadIdx.x;
    if (e >= NE) return;
    int d = dst[e];
    int pos = atomicAdd(&g_off[d], 1);
    g_esrc[pos] = src[e];
    g_edst[pos] = d;
}

// Per-node P,Q for conv1 (FIN=6).
__global__ __launch_bounds__(128)
void node_mlp6(const float* __restrict__ x, const float* __restrict__ W,
               const float* __restrict__ b) {
    __shared__ float sWd[6 * 64];   // Wa - Wb
    __shared__ float sWq[6 * 64];   // Wb
    int tid = threadIdx.x;
    for (int i = tid; i < 6 * 64; i += 128) {
        float wb = W[6 * 64 + i];
        sWd[i] = W[i] - wb;
        sWq[i] = wb;
    }
    __syncthreads();

    int n = blockIdx.x * 128 + tid;
    if (n >= NN) return;
    float xr[6];
#pragma unroll
    for (int j = 0; j < 6; j++) xr[j] = x[(size_t)n * 6 + j];

    float* Pp = g_P + (size_t)n * 64;
    float* Qp = g_Q + (size_t)n * 64;
#pragma unroll 4
    for (int k = 0; k < 64; k++) {
        float p = __ldg(b + k), q = 0.f;
#pragma unroll
        for (int j = 0; j < 6; j++) {
            p = fmaf(xr[j], sWd[j * 64 + k], p);
            q = fmaf(xr[j], sWq[j * 64 + k], q);
        }
        Pp[k] = p;
        Qp[k] = q;
    }
}

// Fused per-node P,Q for conv2: reads g_h1 once (applying deferred lrelu + fix).
__global__ __launch_bounds__(128)
void node_mlp64(const float* __restrict__ W, const float* __restrict__ b) {
    __shared__ float sWdT[64 * 64];  // (Wa-Wb) transposed: [k][j]
    __shared__ float sWqT[64 * 64];  // Wb transposed
    int tid = threadIdx.x;
    for (int i = tid; i < 4096; i += 128) {
        int j = i >> 6, k = i & 63;
        float wb = W[(64 + j) * 64 + k];
        sWdT[k * 64 + j] = W[i] - wb;
        sWqT[k * 64 + j] = wb;
    }
    __syncthreads();

    int n = blockIdx.x * 128 + tid;
    if (n >= NN) return;

    float t[64];
    const float4* hr = (const float4*)(g_h1 + (size_t)n * 64);
#pragma unroll
    for (int q = 0; q < 16; q++) {
        float4 v = hr[q];
        t[4 * q + 0] = fix_act(v.x);
        t[4 * q + 1] = fix_act(v.y);
        t[4 * q + 2] = fix_act(v.z);
        t[4 * q + 3] = fix_act(v.w);
    }

    float* Pp = g_P + (size_t)n * 64;
    float* Qp = g_Q + (size_t)n * 64;
#pragma unroll 1
    for (int k0 = 0; k0 < 64; k0 += 4) {
        float4 pv, qv;
        float* pp = &pv.x;
        float* qp = &qv.x;
#pragma unroll
        for (int kk = 0; kk < 4; kk++) {
            int k = k0 + kk;
            float p0 = __ldg(b + k), p1 = 0.f;
            float q0 = 0.f, q1 = 0.f;
            const float4* wd = (const float4*)(sWdT + k * 64);
            const float4* wq = (const float4*)(sWqT + k * 64);
#pragma unroll
            for (int q = 0; q < 16; q += 2) {
                float4 d0 = wd[q], d1 = wd[q + 1];
                float4 s0 = wq[q], s1 = wq[q + 1];
                p0 = fmaf(t[4*q+0], d0.x, fmaf(t[4*q+1], d0.y, fmaf(t[4*q+2], d0.z, fmaf(t[4*q+3], d0.w, p0))));
                p1 = fmaf(t[4*q+4], d1.x, fmaf(t[4*q+5], d1.y, fmaf(t[4*q+6], d1.z, fmaf(t[4*q+7], d1.w, p1))));
                q0 = fmaf(t[4*q+0], s0.x, fmaf(t[4*q+1], s0.y, fmaf(t[4*q+2], s0.z, fmaf(t[4*q+3], s0.w, q0))));
                q1 = fmaf(t[4*q+4], s1.x, fmaf(t[4*q+5], s1.y, fmaf(t[4*q+6], s1.z, fmaf(t[4*q+7], s1.w, q1))));
            }
            pp[kk] = p0 + p1;
            qp[kk] = q0 + q1;
        }
        ((float4*)Pp)[k0 >> 2] = pv;
        ((float4*)Qp)[k0 >> 2] = qv;
    }
}

// Edge kernel over dst-sorted CSR edges.
// t = lrelu(P[dst]+Q[src]); z = t@Wb + bb (no output lrelu — deferred, monotone);
// warp-segmented suffix-max over same-dst lanes; run leaders atomMaxF to gmem.
template <int PASS>
__global__ __launch_bounds__(128)
void edge_kernel(const float* __restrict__ Wb, const float* __restrict__ bb) {
    __shared__ float sWbT[64 * 64];
    int tid = threadIdx.x;
    for (int i = tid; i < 4096; i += 128) {
        int j = i >> 6, k = i & 63;
        sWbT[k * 64 + j] = Wb[i];
    }
    __syncthreads();

    int e = blockIdx.x * 128 + tid;       // NE divisible by 128 — all lanes valid
    int s = g_esrc[e], d = g_edst[e];

    const float4* Pp = (const float4*)(g_P + (size_t)d * 64);
    const float4* Qp = (const float4*)(g_Q + (size_t)s * 64);
    float t[64];
#pragma unroll
    for (int q = 0; q < 16; q++) {
        float4 a = Pp[q];
        float4 c = Qp[q];
        t[4 * q + 0] = lrelu(a.x + c.x);
        t[4 * q + 1] = lrelu(a.y + c.y);
        t[4 * q + 2] = lrelu(a.z + c.z);
        t[4 * q + 3] = lrelu(a.w + c.w);
    }

    int lane = tid & 31;
    int prevd = __shfl_up_sync(0xffffffffu, d, 1);
    bool leader = (lane == 0) || (prevd != d);
    float* aggd = ((PASS == 1) ? g_h1 : g_h2) + (size_t)d * 64;

#pragma unroll 1
    for (int k0 = 0; k0 < 64; k0 += 8) {
        float o[8];
#pragma unroll
        for (int kk = 0; kk < 8; kk++) {
            int k2 = k0 + kk;
            float a0 = __ldg(bb + k2), a1 = 0.f, a2 = 0.f, a3 = 0.f;
            const float4* wr = (const float4*)(sWbT + k2 * 64);
#pragma unroll
            for (int q = 0; q < 16; q += 4) {
                float4 w0 = wr[q], w1 = wr[q + 1], w2 = wr[q + 2], w3 = wr[q + 3];
                a0 = fmaf(t[4*q+0],  w0.x, fmaf(t[4*q+1],  w0.y, fmaf(t[4*q+2],  w0.z, fmaf(t[4*q+3],  w0.w, a0))));
                a1 = fmaf(t[4*q+4],  w1.x, fmaf(t[4*q+5],  w1.y, fmaf(t[4*q+6],  w1.z, fmaf(t[4*q+7],  w1.w, a1))));
                a2 = fmaf(t[4*q+8],  w2.x, fmaf(t[4*q+9],  w2.y, fmaf(t[4*q+10], w2.z, fmaf(t[4*q+11], w2.w, a2))));
                a3 = fmaf(t[4*q+12], w3.x, fmaf(t[4*q+13], w3.y, fmaf(t[4*q+14], w3.z, fmaf(t[4*q+15], w3.w, a3))));
            }
            o[kk] = (a0 + a1) + (a2 + a3);
        }
        // warp-segmented suffix max over contiguous same-dst lanes
        // (shfl_down clamps at warp edge -> returns own value, harmless self-max)
#pragma unroll
        for (int off = 1; off < 32; off <<= 1) {
            int od = __shfl_down_sync(0xffffffffu, d, off);
            bool same = (od == d);
#pragma unroll
            for (int kk = 0; kk < 8; kk++) {
                float ov = __shfl_down_sync(0xffffffffu, o[kk], off);
                if (same) o[kk] = fmaxf(o[kk], ov);
            }
        }
        if (leader) {
#pragma unroll
            for (int kk = 0; kk < 8; kk++) atomMaxF(aggd + k0 + kk, o[kk]);
        }
    }
}

// One block per graph: mean+max pool g_h2 (deferred lrelu + neg-inf fix inline).
__global__ void pool_kernel(const int* __restrict__ batch) {
    int g = blockIdx.x;
    int lo = 0, hi = NN;
    while (lo < hi) { int m = (lo + hi) >> 1; if (batch[m] < g) lo = m + 1; else hi = m; }
    int start = lo;
    hi = NN;
    while (lo < hi) { int m = (lo + hi) >> 1; if (batch[m] <= g) lo = m + 1; else hi = m; }
    int end = lo;

    int tid = threadIdx.x;
    int k = tid & 63, grp = tid >> 6;
    float s = 0.f;
    float mx = -3.0e38f;
    for (int n = start + grp; n < end; n += 4) {
        float v = fix_act(g_h2[(size_t)n * H + k]);
        s += v;
        mx = fmaxf(mx, v);
    }
    __shared__ float ss[256], sm[256];
    ss[tid] = s; sm[tid] = mx;
    __syncthreads();
    if (grp == 0) {
        s += ss[64 + k] + ss[128 + k] + ss[192 + k];
        mx = fmaxf(fmaxf(mx, sm[64 + k]), fmaxf(sm[128 + k], sm[192 + k]));
        float cnt = (float)((end - start) > 1 ? (end - start) : 1);
        g_gf[g * 128 + k] = s / cnt;
        g_gf[g * 128 + 64 + k] = (end > start) ? mx : 0.f;
    }
}

// 64 blocks x 64 threads: logits = lrelu(g @ Wc1 + bc1) @ Wc2 + bc2
__global__ void cls_kernel(const float* __restrict__ Wc1, const float* __restrict__ bc1,
                           const float* __restrict__ Wc2, const float* __restrict__ bc2,
                           float* __restrict__ out) {
    int g = blockIdx.x, t = threadIdx.x;
    __shared__ float gv[128];
    gv[t] = g_gf[g * 128 + t];
    gv[t + 64] = g_gf[g * 128 + 64 + t];
    __syncthreads();
    float acc = __ldg(bc1 + t);
#pragma unroll 8
    for (int j = 0; j < 128; j++) acc = fmaf(gv[j], Wc1[j * 64 + t], acc);
    float v = lrelu(acc) * __ldg(Wc2 + t);
#pragma unroll
    for (int o = 16; o > 0; o >>= 1) v += __shfl_down_sync(0xffffffffu, v, o);
    __shared__ float part[2];
    if ((t & 31) == 0) part[t >> 5] = v;
    __syncthreads();
    if (t == 0) out[g] = part[0] + part[1] + __ldg(bc2);
}

extern "C" void kernel_launch(void* const* d_in, const int* in_sizes, int n_in,
                              void* d_out, int out_size) {
    const float* x    = (const float*)d_in[0];
    const int*   ei   = (const int*)d_in[1];
    const int*   batch= (const int*)d_in[2];
    const float* W1   = (const float*)d_in[3];
    const float* b1   = (const float*)d_in[4];
    const float* W2   = (const float*)d_in[5];
    const float* b2   = (const float*)d_in[6];
    const float* W3   = (const float*)d_in[7];
    const float* b3   = (const float*)d_in[8];
    const float* W4   = (const float*)d_in[9];
    const float* b4   = (const float*)d_in[10];
    const float* Wc1  = (const float*)d_in[11];
    const float* bc1  = (const float*)d_in[12];
    const float* Wc2  = (const float*)d_in[13];
    const float* bc2  = (const float*)d_in[14];
    float* out = (float*)d_out;

    const int* src = ei;
    const int* dst = ei + NE;

    init_kernel<<<(NN * H / 4 + 255) / 256, 256>>>();
    hist_kernel<<<(NE + 255) / 256, 256>>>(dst);
    scan_kernel<<<1, 1024>>>();
    scatter_kernel<<<(NE + 255) / 256, 256>>>(src, dst);
    node_mlp6<<<(NN + 127) / 128, 128>>>(x, W1, b1);
    edge_kernel<1><<<NE / 128, 128>>>(W2, b2);
    node_mlp64<<<(NN + 127) / 128, 128>>>(W3, b3);
    edge_kernel<2><<<NE / 128, 128>>>(W4, b4);
    pool_kernel<<<NG, 256>>>(batch);
    cls_kernel<<<NG, 64>>>(Wc1, bc1, Wc2, bc2, out);
}

// round 5
// speedup vs baseline: 2.6322x; 1.5607x over previous
#include <cuda_runtime.h>
#include <cuda_bf16.h>
#include <cstdint>

#define NN 50000
#define NE 1280000
#define NG 64
#define H  64
#define NEG_BITS 0xFF800000u

// Scratch (device globals; allocation forbidden)
__device__ float g_h1[NN * H];   // conv1 aggregate (pre-bias, pre-activation max)
__device__ float g_h2[NN * H];   // conv2 aggregate (pre-bias, pre-activation max)
__device__ float g_P[NN * H];
__device__ float g_Q[NN * H];
__device__ float g_gf[NG * 2 * H];
__device__ int   g_cnt[NN + 1];
__device__ int   g_off[NN + 1];
__device__ int   g_esrc[NE];
__device__ int   g_edst[NE];
// Split transposed weights for the two edge GEMMs: [conv][n(=out)*64 + j(=in)], bf16 hi/lo
__device__ __nv_bfloat16 g_WhT[2][4096];
__device__ __nv_bfloat16 g_WlT[2][4096];

__device__ __forceinline__ float lrelu(float x) { return fmaxf(x, 0.2f * x); }

__device__ __forceinline__ void atomMaxF(float* a, float v) {
    int bi = __float_as_int(v);
    if (bi == (int)0x80000000) bi = 0;
    if (bi >= 0) atomicMax((int*)a, bi);
    else         atomicMin((unsigned int*)a, (unsigned int)bi);
}

__device__ __forceinline__ uint32_t smem_u32(const void* p) {
    uint32_t a;
    asm("{ .reg .u64 t; cvta.to.shared.u64 t, %1; cvt.u32.u64 %0, t; }" : "=r"(a) : "l"(p));
    return a;
}
__device__ __forceinline__ uint32_t lds32(uint32_t a) {
    uint32_t v;
    asm volatile("ld.shared.b32 %0, [%1];" : "=r"(v) : "r"(a));
    return v;
}
__device__ __forceinline__ void sts32(uint32_t a, uint32_t v) {
    asm volatile("st.shared.b32 [%0], %1;" :: "r"(a), "r"(v) : "memory");
}
__device__ __forceinline__ void sts_v2f(uint32_t a, float x, float y) {
    asm volatile("st.shared.v2.f32 [%0], {%1,%2};" :: "r"(a), "f"(x), "f"(y) : "memory");
}
__device__ __forceinline__ float ldsf(uint32_t a) {
    float v;
    asm volatile("ld.shared.f32 %0, [%1];" : "=f"(v) : "r"(a));
    return v;
}

// Warp-level bf16 tensor op (plain sm_103-compatible, HMMA path)
__device__ __forceinline__ void mma16816(float c[4], const uint32_t a[4], uint32_t b0, uint32_t b1) {
    asm volatile(
        "mma.sync.aligned.m16n8k16.row.col.f32.bf16.bf16.f32 "
        "{%0,%1,%2,%3}, {%4,%5,%6,%7}, {%8,%9}, {%0,%1,%2,%3};"
        : "+f"(c[0]), "+f"(c[1]), "+f"(c[2]), "+f"(c[3])
        : "r"(a[0]), "r"(a[1]), "r"(a[2]), "r"(a[3]), "r"(b0), "r"(b1));
}

// ---------- setup kernels ----------
__global__ void init_kernel() {
    int i = blockIdx.x * blockDim.x + threadIdx.x;
    float ni = __int_as_float((int)NEG_BITS);
    float4 v = make_float4(ni, ni, ni, ni);
    if (i < NN * H / 4) {
        ((float4*)g_h1)[i] = v;
        ((float4*)g_h2)[i] = v;
    }
    if (i <= NN) g_cnt[i] = 0;
}

__global__ void prep_w(const float* __restrict__ W2, const float* __restrict__ W4) {
    int i = blockIdx.x * blockDim.x + threadIdx.x;
    if (i >= 8192) return;
    int c = i >> 12, idx = i & 4095;
    const float* W = c ? W4 : W2;
    int n = idx >> 6, j = idx & 63;       // B[n][j] = W[j][n]
    float w = W[j * 64 + n];
    __nv_bfloat16 h = __float2bfloat16_rn(w);
    g_WhT[c][idx] = h;
    g_WlT[c][idx] = __float2bfloat16_rn(w - __bfloat162float(h));
}

__global__ void hist_kernel(const int* __restrict__ dst) {
    int e = blockIdx.x * blockDim.x + threadIdx.x;
    if (e < NE) atomicAdd(&g_cnt[dst[e]], 1);
}

__global__ void scan_kernel() {
    __shared__ int sums[1024];
    const int CH = (NN + 1023) / 1024;
    int tid = threadIdx.x;
    int base = tid * CH;
    int s = 0;
    for (int i = 0; i < CH; i++) { int idx = base + i; if (idx < NN) s += g_cnt[idx]; }
    sums[tid] = s;
    __syncthreads();
    for (int off = 1; off < 1024; off <<= 1) {
        int v = (tid >= off) ? sums[tid - off] : 0;
        __syncthreads();
        sums[tid] += v;
        __syncthreads();
    }
    int run = (tid == 0) ? 0 : sums[tid - 1];
    for (int i = 0; i < CH; i++) {
        int idx = base + i;
        if (idx < NN) { int c = g_cnt[idx]; g_off[idx] = run; run += c; }
    }
}

__global__ void scatter_kernel(const int* __restrict__ src, const int* __restrict__ dst) {
    int e = blockIdx.x * blockDim.x + threadIdx.x;
    if (e >= NE) return;
    int d = dst[e];
    int pos = atomicAdd(&g_off[d], 1);
    g_esrc[pos] = src[e];
    g_edst[pos] = d;
}

// ---------- node MLPs ----------
__global__ __launch_bounds__(128)
void node_mlp6(const float* __restrict__ x, const float* __restrict__ W,
               const float* __restrict__ b) {
    __shared__ float sWd[6 * 64];
    __shared__ float sWq[6 * 64];
    int tid = threadIdx.x;
    for (int i = tid; i < 6 * 64; i += 128) {
        float wb = W[6 * 64 + i];
        sWd[i] = W[i] - wb;
        sWq[i] = wb;
    }
    __syncthreads();
    int n = blockIdx.x * 128 + tid;
    if (n >= NN) return;
    float xr[6];
#pragma unroll
    for (int j = 0; j < 6; j++) xr[j] = x[(size_t)n * 6 + j];
    float* Pp = g_P + (size_t)n * 64;
    float* Qp = g_Q + (size_t)n * 64;
#pragma unroll 4
    for (int k = 0; k < 64; k++) {
        float p = __ldg(b + k), q = 0.f;
#pragma unroll
        for (int j = 0; j < 6; j++) {
            p = fmaf(xr[j], sWd[j * 64 + k], p);
            q = fmaf(xr[j], sWq[j * 64 + k], q);
        }
        Pp[k] = p;
        Qp[k] = q;
    }
}

// conv2 P,Q from g_h1 (deferred bias bprev + lrelu + neg-inf fix applied here).
__global__ __launch_bounds__(128)
void node_mlp64(const float* __restrict__ W, const float* __restrict__ b,
                const float* __restrict__ bprev) {
    __shared__ float sWdT[64 * 64];
    __shared__ float sWqT[64 * 64];
    __shared__ float sbp[64];
    int tid = threadIdx.x;
    for (int i = tid; i < 4096; i += 128) {
        int j = i >> 6, k = i & 63;
        float wb = W[(64 + j) * 64 + k];
        sWdT[k * 64 + j] = W[i] - wb;
        sWqT[k * 64 + j] = wb;
    }
    if (tid < 64) sbp[tid] = bprev[tid];
    __syncthreads();

    int n = blockIdx.x * 128 + tid;
    if (n >= NN) return;

    float t[64];
    const float4* hr = (const float4*)(g_h1 + (size_t)n * 64);
#pragma unroll
    for (int q = 0; q < 16; q++) {
        float4 v = hr[q];
        float* tp = t + 4 * q;
        float* vp = &v.x;
#pragma unroll
        for (int kk = 0; kk < 4; kk++) {
            float z = vp[kk];
            tp[kk] = (__float_as_int(z) == (int)NEG_BITS) ? 0.f : lrelu(z + sbp[4 * q + kk]);
        }
    }

    float* Pp = g_P + (size_t)n * 64;
    float* Qp = g_Q + (size_t)n * 64;
#pragma unroll 1
    for (int k0 = 0; k0 < 64; k0 += 4) {
        float4 pv, qv;
        float* pp = &pv.x;
        float* qp = &qv.x;
#pragma unroll
        for (int kk = 0; kk < 4; kk++) {
            int k = k0 + kk;
            float p0 = __ldg(b + k), p1 = 0.f, q0 = 0.f, q1 = 0.f;
            const float4* wd = (const float4*)(sWdT + k * 64);
            const float4* wq = (const float4*)(sWqT + k * 64);
#pragma unroll
            for (int q = 0; q < 16; q += 2) {
                float4 d0 = wd[q], d1 = wd[q + 1];
                float4 s0 = wq[q], s1 = wq[q + 1];
                p0 = fmaf(t[4*q+0], d0.x, fmaf(t[4*q+1], d0.y, fmaf(t[4*q+2], d0.z, fmaf(t[4*q+3], d0.w, p0))));
                p1 = fmaf(t[4*q+4], d1.x, fmaf(t[4*q+5], d1.y, fmaf(t[4*q+6], d1.z, fmaf(t[4*q+7], d1.w, p1))));
                q0 = fmaf(t[4*q+0], s0.x, fmaf(t[4*q+1], s0.y, fmaf(t[4*q+2], s0.z, fmaf(t[4*q+3], s0.w, q0))));
                q1 = fmaf(t[4*q+4], s1.x, fmaf(t[4*q+5], s1.y, fmaf(t[4*q+6], s1.z, fmaf(t[4*q+7], s1.w, q1))));
            }
            pp[kk] = p0 + p1;
            qp[kk] = q0 + q1;
        }
        ((float4*)Pp)[k0 >> 2] = pv;
        ((float4*)Qp)[k0 >> 2] = qv;
    }
}

// ---------- mma.sync edge kernel ----------
// CTA = 128 dst-sorted edges, 4 warps. Each warp: M=32 edges x N=64 x K=64,
// bf16 hi/lo 3-term split via mma.sync.m16n8k16 (fp32 acc, bias deferred).
// A/B padded smem (132B rows); D staged via smem; warp-segmented max + leader atomics.
// Smem map (bytes from base): Ah[0,16896) Al[16896,33792) Bh[33792,42240) Bl[42240,50688)
// D (fp32, 128 x 66-stride = 33792B) reuses [0,33792) after syncthreads.
template <int PASS>
__global__ __launch_bounds__(128, 4)
void edge_mma_kernel() {
    extern __shared__ char dsm_raw[];
    uint32_t base = smem_u32(dsm_raw);
    uint32_t sAh = base;
    uint32_t sAl = base + 16896;
    uint32_t sBh = base + 33792;
    uint32_t sBl = base + 42240;

    int tid = threadIdx.x;
    int wid = tid >> 5, lane = tid & 31;
    int gq = lane >> 2, tq = lane & 3;

    // Stage B hi/lo ([n][k] bf16, padded 132B rows)
    const uint32_t* Bh32 = (const uint32_t*)g_WhT[PASS - 1];
    const uint32_t* Bl32 = (const uint32_t*)g_WlT[PASS - 1];
#pragma unroll
    for (int it = 0; it < 16; it++) {
        int i = tid + it * 128;            // b32 index, 2048 total
        int n = i >> 5, kc = i & 31;
        uint32_t off = (uint32_t)(n * 132 + kc * 4);
        sts32(sBh + off, Bh32[i]);
        sts32(sBl + off, Bl32[i]);
    }

    // Per-edge t = lrelu(P[dst]+Q[src]) -> bf16 hi/lo row in smem
    int e = blockIdx.x * 128 + tid;        // NE % 128 == 0
    int s = g_esrc[e], d = g_edst[e];
    {
        const float4* Pp = (const float4*)(g_P + (size_t)d * 64);
        const float4* Qp = (const float4*)(g_Q + (size_t)s * 64);
        uint32_t arow = (uint32_t)(tid * 132);
#pragma unroll
        for (int q = 0; q < 16; q++) {
            float4 a = Pp[q];
            float4 c = Qp[q];
            float t0 = lrelu(a.x + c.x), t1 = lrelu(a.y + c.y);
            float t2 = lrelu(a.z + c.z), t3 = lrelu(a.w + c.w);
            __nv_bfloat16 h0 = __float2bfloat16_rn(t0), h1 = __float2bfloat16_rn(t1);
            __nv_bfloat16 h2 = __float2bfloat16_rn(t2), h3 = __float2bfloat16_rn(t3);
            uint32_t hi0 = (uint32_t)__bfloat16_as_ushort(h0) | ((uint32_t)__bfloat16_as_ushort(h1) << 16);
            uint32_t hi1 = (uint32_t)__bfloat16_as_ushort(h2) | ((uint32_t)__bfloat16_as_ushort(h3) << 16);
            __nv_bfloat16 l0 = __float2bfloat16_rn(t0 - __bfloat162float(h0));
            __nv_bfloat16 l1 = __float2bfloat16_rn(t1 - __bfloat162float(h1));
            __nv_bfloat16 l2 = __float2bfloat16_rn(t2 - __bfloat162float(h2));
            __nv_bfloat16 l3 = __float2bfloat16_rn(t3 - __bfloat162float(h3));
            uint32_t lo0 = (uint32_t)__bfloat16_as_ushort(l0) | ((uint32_t)__bfloat16_as_ushort(l1) << 16);
            uint32_t lo1 = (uint32_t)__bfloat16_as_ushort(l2) | ((uint32_t)__bfloat16_as_ushort(l3) << 16);
            sts32(sAh + arow + q * 8, hi0);
            sts32(sAh + arow + q * 8 + 4, hi1);
            sts32(sAl + arow + q * 8, lo0);
            sts32(sAl + arow + q * 8 + 4, lo1);
        }
    }
    __syncthreads();

    // MMA mainloop
    float acc[2][8][4];
#pragma unroll
    for (int mt = 0; mt < 2; mt++)
#pragma unroll
        for (int nt = 0; nt < 8; nt++)
#pragma unroll
            for (int r = 0; r < 4; r++) acc[mt][nt][r] = 0.f;

#pragma unroll
    for (int kt = 0; kt < 4; kt++) {
        uint32_t ah[2][4], al[2][4];
#pragma unroll
        for (int mt = 0; mt < 2; mt++) {
            int r0 = wid * 32 + mt * 16 + gq;
            uint32_t o0 = (uint32_t)(r0 * 132 + kt * 32 + tq * 4);
            uint32_t o1 = o0 + 8 * 132;
            ah[mt][0] = lds32(sAh + o0); ah[mt][2] = lds32(sAh + o0 + 16);
            ah[mt][1] = lds32(sAh + o1); ah[mt][3] = lds32(sAh + o1 + 16);
            al[mt][0] = lds32(sAl + o0); al[mt][2] = lds32(sAl + o0 + 16);
            al[mt][1] = lds32(sAl + o1); al[mt][3] = lds32(sAl + o1 + 16);
        }
#pragma unroll
        for (int nt = 0; nt < 8; nt++) {
            uint32_t ob = (uint32_t)((nt * 8 + gq) * 132 + kt * 32 + tq * 4);
            uint32_t bh0 = lds32(sBh + ob), bh1 = lds32(sBh + ob + 16);
            uint32_t bl0 = lds32(sBl + ob), bl1 = lds32(sBl + ob + 16);
#pragma unroll
            for (int mt = 0; mt < 2; mt++) {
                mma16816(acc[mt][nt], ah[mt], bh0, bh1);
                mma16816(acc[mt][nt], ah[mt], bl0, bl1);
                mma16816(acc[mt][nt], al[mt], bh0, bh1);
            }
        }
    }

    // Stage D to smem (fp32, stride 66 floats), then per-thread row readback
    __syncthreads();
    uint32_t sD = base;
#pragma unroll
    for (int mt = 0; mt < 2; mt++) {
        int row0 = wid * 32 + mt * 16 + gq;
#pragma unroll
        for (int nt = 0; nt < 8; nt++) {
            uint32_t o = (uint32_t)((row0 * 66 + nt * 8 + tq * 2) * 4);
            sts_v2f(sD + o, acc[mt][nt][0], acc[mt][nt][1]);
            sts_v2f(sD + o + 8 * 66 * 4, acc[mt][nt][2], acc[mt][nt][3]);
        }
    }
    __syncwarp();

    int prevd = __shfl_up_sync(0xffffffffu, d, 1);
    bool leader = (lane == 0) || (prevd != d);
    float* aggd = ((PASS == 1) ? g_h1 : g_h2) + (size_t)d * 64;
    uint32_t rbase = sD + (uint32_t)(tid * 66 * 4);

#pragma unroll 1
    for (int half = 0; half < 2; half++) {
        float o[32];
#pragma unroll
        for (int i = 0; i < 32; i++) o[i] = ldsf(rbase + (uint32_t)((half * 32 + i) * 4));
        // warp-segmented suffix max over contiguous same-dst lanes
#pragma unroll
        for (int off = 1; off < 32; off <<= 1) {
            int od = __shfl_down_sync(0xffffffffu, d, off);
            bool same = (od == d);
#pragma unroll
            for (int i = 0; i < 32; i++) {
                float ov = __shfl_down_sync(0xffffffffu, o[i], off);
                if (same) o[i] = fmaxf(o[i], ov);
            }
        }
        if (leader) {
#pragma unroll
            for (int i = 0; i < 32; i++) atomMaxF(aggd + half * 32 + i, o[i]);
        }
    }
}

// ---------- pooling / classifier ----------
__global__ void pool_kernel(const int* __restrict__ batch, const float* __restrict__ bprev) {
    int g = blockIdx.x;
    int lo = 0, hi = NN;
    while (lo < hi) { int m = (lo + hi) >> 1; if (batch[m] < g) lo = m + 1; else hi = m; }
    int start = lo;
    hi = NN;
    while (lo < hi) { int m = (lo + hi) >> 1; if (batch[m] <= g) lo = m + 1; else hi = m; }
    int end = lo;

    int tid = threadIdx.x;
    int k = tid & 63, grp = tid >> 6;
    float bk = __ldg(bprev + k);
    float s = 0.f;
    float mx = -3.0e38f;
    for (int n = start + grp; n < end; n += 4) {
        float z = g_h2[(size_t)n * H + k];
        float v = (__float_as_int(z) == (int)NEG_BITS) ? 0.f : lrelu(z + bk);
        s += v;
        mx = fmaxf(mx, v);
    }
    __shared__ float ss[256], sm[256];
    ss[tid] = s; sm[tid] = mx;
    __syncthreads();
    if (grp == 0) {
        s += ss[64 + k] + ss[128 + k] + ss[192 + k];
        mx = fmaxf(fmaxf(mx, sm[64 + k]), fmaxf(sm[128 + k], sm[192 + k]));
        float cnt = (float)((end - start) > 1 ? (end - start) : 1);
        g_gf[g * 128 + k] = s / cnt;
        g_gf[g * 128 + 64 + k] = (end > start) ? mx : 0.f;
    }
}

__global__ void cls_kernel(const float* __restrict__ Wc1, const float* __restrict__ bc1,
                           const float* __restrict__ Wc2, const float* __restrict__ bc2,
                           float* __restrict__ out) {
    int g = blockIdx.x, t = threadIdx.x;
    __shared__ float gv[128];
    gv[t] = g_gf[g * 128 + t];
    gv[t + 64] = g_gf[g * 128 + 64 + t];
    __syncthreads();
    float acc = __ldg(bc1 + t);
#pragma unroll 8
    for (int j = 0; j < 128; j++) acc = fmaf(gv[j], Wc1[j * 64 + t], acc);
    float v = lrelu(acc) * __ldg(Wc2 + t);
#pragma unroll
    for (int o = 16; o > 0; o >>= 1) v += __shfl_down_sync(0xffffffffu, v, o);
    __shared__ float part[2];
    if ((t & 31) == 0) part[t >> 5] = v;
    __syncthreads();
    if (t == 0) out[g] = part[0] + part[1] + __ldg(bc2);
}

extern "C" void kernel_launch(void* const* d_in, const int* in_sizes, int n_in,
                              void* d_out, int out_size) {
    const float* x    = (const float*)d_in[0];
    const int*   ei   = (const int*)d_in[1];
    const int*   batch= (const int*)d_in[2];
    const float* W1   = (const float*)d_in[3];
    const float* b1   = (const float*)d_in[4];
    const float* W2   = (const float*)d_in[5];
    const float* b2   = (const float*)d_in[6];
    const float* W3   = (const float*)d_in[7];
    const float* b3   = (const float*)d_in[8];
    const float* W4   = (const float*)d_in[9];
    const float* b4   = (const float*)d_in[10];
    const float* Wc1  = (const float*)d_in[11];
    const float* bc1  = (const float*)d_in[12];
    const float* Wc2  = (const float*)d_in[13];
    const float* bc2  = (const float*)d_in[14];
    float* out = (float*)d_out;

    const int* src = ei;
    const int* dst = ei + NE;

    const int DSM = 50688;
    cudaFuncSetAttribute(edge_mma_kernel<1>, cudaFuncAttributeMaxDynamicSharedMemorySize, DSM);
    cudaFuncSetAttribute(edge_mma_kernel<2>, cudaFuncAttributeMaxDynamicSharedMemorySize, DSM);

    init_kernel<<<(NN * H / 4 + 255) / 256, 256>>>();
    prep_w<<<32, 256>>>(W2, W4);
    hist_kernel<<<(NE + 255) / 256, 256>>>(dst);
    scan_kernel<<<1, 1024>>>();
    scatter_kernel<<<(NE + 255) / 256, 256>>>(src, dst);
    node_mlp6<<<(NN + 127) / 128, 128>>>(x, W1, b1);
    edge_mma_kernel<1><<<NE / 128, 128, DSM>>>();
    node_mlp64<<<(NN + 127) / 128, 128>>>(W3, b3, b2);
    edge_mma_kernel<2><<<NE / 128, 128, DSM>>>();
    pool_kernel<<<NG, 256>>>(batch, b4);
    cls_kernel<<<NG, 64>>>(Wc1, bc1, Wc2, bc2, out);
}

// round 6
// speedup vs baseline: 4.1680x; 1.5835x over previous
#include <cuda_runtime.h>
#include <cuda_bf16.h>
#include <cstdint>

#define NN 50000
#define NE 1280000
#define NG 64
#define H  64
#define NEG_BITS 0xFF800000u

// Scratch (device globals; allocation forbidden)
__device__ float g_h1[NN * H];   // conv1 aggregate (pre-bias, pre-activation max)
__device__ float g_h2[NN * H];   // conv2 aggregate (pre-bias, pre-activation max)
__device__ float g_P[NN * H];
__device__ float g_Q[NN * H];
__device__ float g_gf[NG * 2 * H];
__device__ int   g_cnt[NN + 1];
__device__ int   g_off[NN + 1];
__device__ int   g_bsum[128];
__device__ int   g_esrc[NE];
__device__ int   g_edst[NE];
// Split transposed weights for the two edge GEMMs: [conv][n(=out)*64 + j(=in)], bf16 hi/lo
__device__ __nv_bfloat16 g_WhT[2][4096];
__device__ __nv_bfloat16 g_WlT[2][4096];

__device__ __forceinline__ float lrelu(float x) { return fmaxf(x, 0.2f * x); }

__device__ __forceinline__ void atomMaxF(float* a, float v) {
    int bi = __float_as_int(v);
    if (bi == (int)0x80000000) bi = 0;
    if (bi >= 0) atomicMax((int*)a, bi);
    else         atomicMin((unsigned int*)a, (unsigned int)bi);
}

__device__ __forceinline__ uint32_t smem_u32(const void* p) {
    uint32_t a;
    asm("{ .reg .u64 t; cvta.to.shared.u64 t, %1; cvt.u32.u64 %0, t; }" : "=r"(a) : "l"(p));
    return a;
}
__device__ __forceinline__ uint32_t lds32(uint32_t a) {
    uint32_t v;
    asm volatile("ld.shared.b32 %0, [%1];" : "=r"(v) : "r"(a));
    return v;
}
__device__ __forceinline__ void sts32(uint32_t a, uint32_t v) {
    asm volatile("st.shared.b32 [%0], %1;" :: "r"(a), "r"(v) : "memory");
}
__device__ __forceinline__ void sts_v4(uint32_t a, uint32_t x, uint32_t y, uint32_t z, uint32_t w) {
    asm volatile("st.shared.v4.b32 [%0], {%1,%2,%3,%4};" :: "r"(a), "r"(x), "r"(y), "r"(z), "r"(w) : "memory");
}
__device__ __forceinline__ void sts_v2f(uint32_t a, float x, float y) {
    asm volatile("st.shared.v2.f32 [%0], {%1,%2};" :: "r"(a), "f"(x), "f"(y) : "memory");
}
__device__ __forceinline__ float ldsf(uint32_t a) {
    float v;
    asm volatile("ld.shared.f32 %0, [%1];" : "=f"(v) : "r"(a));
    return v;
}
// packed bf16x2 convert: hi arg -> upper 16 bits, lo arg -> lower 16 bits
__device__ __forceinline__ uint32_t cvt2bf(float hi, float lo) {
    uint32_t r;
    asm("cvt.rn.bf16x2.f32 %0, %1, %2;" : "=r"(r) : "f"(hi), "f"(lo));
    return r;
}

// Warp-level bf16 tensor op (plain sm_103-compatible, HMMA path)
__device__ __forceinline__ void mma16816(float c[4], const uint32_t a[4], uint32_t b0, uint32_t b1) {
    asm volatile(
        "mma.sync.aligned.m16n8k16.row.col.f32.bf16.bf16.f32 "
        "{%0,%1,%2,%3}, {%4,%5,%6,%7}, {%8,%9}, {%0,%1,%2,%3};"
        : "+f"(c[0]), "+f"(c[1]), "+f"(c[2]), "+f"(c[3])
        : "r"(a[0]), "r"(a[1]), "r"(a[2]), "r"(a[3]), "r"(b0), "r"(b1));
}

// ---------- setup kernels ----------
__global__ void init_kernel() {
    int i = blockIdx.x * blockDim.x + threadIdx.x;
    float ni = __int_as_float((int)NEG_BITS);
    float4 v = make_float4(ni, ni, ni, ni);
    if (i < NN * H / 4) {
        ((float4*)g_h1)[i] = v;
        ((float4*)g_h2)[i] = v;
    }
    if (i <= NN) g_cnt[i] = 0;
}

__global__ void prep_w(const float* __restrict__ W2, const float* __restrict__ W4) {
    int i = blockIdx.x * blockDim.x + threadIdx.x;
    if (i >= 8192) return;
    int c = i >> 12, idx = i & 4095;
    const float* W = c ? W4 : W2;
    int n = idx >> 6, j = idx & 63;       // B[n][j] = W[j][n]
    float w = W[j * 64 + n];
    __nv_bfloat16 h = __float2bfloat16_rn(w);
    g_WhT[c][idx] = h;
    g_WlT[c][idx] = __float2bfloat16_rn(w - __bfloat162float(h));
}

__global__ void hist_kernel(const int* __restrict__ dst) {
    int e = blockIdx.x * blockDim.x + threadIdx.x;
    if (e < NE) atomicAdd(&g_cnt[dst[e]], 1);
}

// Parallel scan: per-block exclusive scan + block totals
__global__ void bscan_kernel() {
    int tid = threadIdx.x;
    int i = blockIdx.x * 512 + tid;
    int v = (i < NN) ? g_cnt[i] : 0;
    int lane = tid & 31, wid = tid >> 5;
    int x = v;
#pragma unroll
    for (int o = 1; o < 32; o <<= 1) {
        int y = __shfl_up_sync(0xffffffffu, x, o);
        if (lane >= o) x += y;
    }
    __shared__ int ws[16];
    if (lane == 31) ws[wid] = x;
    __syncthreads();
    if (wid == 0 && lane < 16) {
        int y = ws[lane];
#pragma unroll
        for (int o = 1; o < 16; o <<= 1) {
            int z = __shfl_up_sync(0xffffu, y, o);
            if (lane >= o) y += z;
        }
        ws[lane] = y;
    }
    __syncthreads();
    int base = wid ? ws[wid - 1] : 0;
    if (i < NN) g_off[i] = base + x - v;
    if (tid == 511) g_bsum[blockIdx.x] = base + x;
}

__global__ void topscan_kernel(int nb) {
    __shared__ int s[128];
    int t = threadIdx.x;
    s[t] = (t < nb) ? g_bsum[t] : 0;
    __syncthreads();
    for (int o = 1; o < 128; o <<= 1) {
        int v = (t >= o) ? s[t - o] : 0;
        __syncthreads();
        s[t] += v;
        __syncthreads();
    }
    if (t < nb) g_bsum[t] = (t == 0) ? 0 : s[t - 1];
}

__global__ void addoff_kernel() {
    int i = blockIdx.x * 512 + threadIdx.x;
    if (i < NN) g_off[i] += g_bsum[i >> 9];
}

__global__ void scatter_kernel(const int* __restrict__ src, const int* __restrict__ dst) {
    int e = blockIdx.x * blockDim.x + threadIdx.x;
    if (e >= NE) return;
    int d = dst[e];
    int pos = atomicAdd(&g_off[d], 1);
    g_esrc[pos] = src[e];
    g_edst[pos] = d;
}

// ---------- node MLPs ----------
__global__ __launch_bounds__(128)
void node_mlp6(const float* __restrict__ x, const float* __restrict__ W,
               const float* __restrict__ b) {
    __shared__ float sWd[6 * 64];
    __shared__ float sWq[6 * 64];
    int tid = threadIdx.x;
    for (int i = tid; i < 6 * 64; i += 128) {
        float wb = W[6 * 64 + i];
        sWd[i] = W[i] - wb;
        sWq[i] = wb;
    }
    __syncthreads();
    int n = blockIdx.x * 128 + tid;
    if (n >= NN) return;
    float xr[6];
#pragma unroll
    for (int j = 0; j < 6; j++) xr[j] = x[(size_t)n * 6 + j];
    float* Pp = g_P + (size_t)n * 64;
    float* Qp = g_Q + (size_t)n * 64;
#pragma unroll 4
    for (int k = 0; k < 64; k++) {
        float p = __ldg(b + k), q = 0.f;
#pragma unroll
        for (int j = 0; j < 6; j++) {
            p = fmaf(xr[j], sWd[j * 64 + k], p);
            q = fmaf(xr[j], sWq[j * 64 + k], q);
        }
        Pp[k] = p;
        Qp[k] = q;
    }
}

// conv2 P,Q from g_h1 (deferred bias bprev + lrelu + neg-inf fix applied here).
__global__ __launch_bounds__(128)
void node_mlp64(const float* __restrict__ W, const float* __restrict__ b,
                const float* __restrict__ bprev) {
    __shared__ float sWdT[64 * 64];
    __shared__ float sWqT[64 * 64];
    __shared__ float sbp[64];
    int tid = threadIdx.x;
    for (int i = tid; i < 4096; i += 128) {
        int j = i >> 6, k = i & 63;
        float wb = W[(64 + j) * 64 + k];
        sWdT[k * 64 + j] = W[i] - wb;
        sWqT[k * 64 + j] = wb;
    }
    if (tid < 64) sbp[tid] = bprev[tid];
    __syncthreads();

    int n = blockIdx.x * 128 + tid;
    if (n >= NN) return;

    float t[64];
    const float4* hr = (const float4*)(g_h1 + (size_t)n * 64);
#pragma unroll
    for (int q = 0; q < 16; q++) {
        float4 v = hr[q];
        float* tp = t + 4 * q;
        float* vp = &v.x;
#pragma unroll
        for (int kk = 0; kk < 4; kk++) {
            float z = vp[kk];
            tp[kk] = (__float_as_int(z) == (int)NEG_BITS) ? 0.f : lrelu(z + sbp[4 * q + kk]);
        }
    }

    float* Pp = g_P + (size_t)n * 64;
    float* Qp = g_Q + (size_t)n * 64;
#pragma unroll 1
    for (int k0 = 0; k0 < 64; k0 += 4) {
        float4 pv, qv;
        float* pp = &pv.x;
        float* qp = &qv.x;
#pragma unroll
        for (int kk = 0; kk < 4; kk++) {
            int k = k0 + kk;
            float p0 = __ldg(b + k), p1 = 0.f, q0 = 0.f, q1 = 0.f;
            const float4* wd = (const float4*)(sWdT + k * 64);
            const float4* wq = (const float4*)(sWqT + k * 64);
#pragma unroll
            for (int q = 0; q < 16; q += 2) {
                float4 d0 = wd[q], d1 = wd[q + 1];
                float4 s0 = wq[q], s1 = wq[q + 1];
                p0 = fmaf(t[4*q+0], d0.x, fmaf(t[4*q+1], d0.y, fmaf(t[4*q+2], d0.z, fmaf(t[4*q+3], d0.w, p0))));
                p1 = fmaf(t[4*q+4], d1.x, fmaf(t[4*q+5], d1.y, fmaf(t[4*q+6], d1.z, fmaf(t[4*q+7], d1.w, p1))));
                q0 = fmaf(t[4*q+0], s0.x, fmaf(t[4*q+1], s0.y, fmaf(t[4*q+2], s0.z, fmaf(t[4*q+3], s0.w, q0))));
                q1 = fmaf(t[4*q+4], s1.x, fmaf(t[4*q+5], s1.y, fmaf(t[4*q+6], s1.z, fmaf(t[4*q+7], s1.w, q1))));
            }
            pp[kk] = p0 + p1;
            qp[kk] = q0 + q1;
        }
        ((float4*)Pp)[k0 >> 2] = pv;
        ((float4*)Qp)[k0 >> 2] = qv;
    }
}

// ---------- mma.sync edge kernel (conflict-free swizzled smem) ----------
// Smem map (bytes from base): Ah[0,16384) Al[16384,32768) Bh[32768,40960) Bl[40960,49152)
// sDst [49152,49664). D (fp32, 128 rows x 256B swizzled) reuses [0,32768).
// A/B: 128B rows, SW128 XOR swizzle (16B chunk ^ (row%8)).
// D: 256B rows, 32B-granule XOR swizzle (granule ^ (row%8)).
template <int PASS>
__global__ __launch_bounds__(128, 4)
void edge_mma_kernel() {
    extern __shared__ char dsm_raw[];
    uint32_t base = smem_u32(dsm_raw);
    uint32_t sAh = base;
    uint32_t sAl = base + 16384;
    uint32_t sBh = base + 32768;
    uint32_t sBl = base + 40960;
    int* sDst = (int*)(dsm_raw + 49152);

    int tid = threadIdx.x;
    int wid = tid >> 5, lane = tid & 31;
    int gq = lane >> 2, tq = lane & 3;

    // Stage B hi/lo: row n (128B, only first 128B used per row), SW128 swizzle
    const uint32_t* Bh32 = (const uint32_t*)g_WhT[PASS - 1];
    const uint32_t* Bl32 = (const uint32_t*)g_WlT[PASS - 1];
#pragma unroll
    for (int it = 0; it < 16; it++) {
        int i = tid + it * 128;            // 2048 uint32 per plane
        int n = i >> 5, jc = i & 31;
        uint32_t off = (uint32_t)(n * 128) + (((uint32_t)(jc * 4)) ^ ((uint32_t)(n & 7) << 4));
        sts32(sBh + off, Bh32[i]);
        sts32(sBl + off, Bl32[i]);
    }

    // Per-edge t = lrelu(P[dst]+Q[src]) -> bf16 hi/lo row (SW128 swizzled)
    int e = blockIdx.x * 128 + tid;        // NE % 128 == 0
    int s = g_esrc[e], d = g_edst[e];
    sDst[tid] = d;
    {
        const float4* Pp = (const float4*)(g_P + (size_t)d * 64);
        const float4* Qp = (const float4*)(g_Q + (size_t)s * 64);
        uint32_t arow = (uint32_t)(tid * 128);
        uint32_t xA = (uint32_t)(tid & 7) << 4;
#pragma unroll
        for (int g = 0; g < 8; g++) {
            float4 a0 = Pp[2 * g],     c0 = Qp[2 * g];
            float4 a1 = Pp[2 * g + 1], c1 = Qp[2 * g + 1];
            float t0 = lrelu(a0.x + c0.x), t1 = lrelu(a0.y + c0.y);
            float t2 = lrelu(a0.z + c0.z), t3 = lrelu(a0.w + c0.w);
            float t4 = lrelu(a1.x + c1.x), t5 = lrelu(a1.y + c1.y);
            float t6 = lrelu(a1.z + c1.z), t7 = lrelu(a1.w + c1.w);
            uint32_t h0 = cvt2bf(t1, t0), h1 = cvt2bf(t3, t2);
            uint32_t h2 = cvt2bf(t5, t4), h3 = cvt2bf(t7, t6);
            uint32_t l0 = cvt2bf(t1 - __uint_as_float(h0 & 0xFFFF0000u), t0 - __uint_as_float(h0 << 16));
            uint32_t l1 = cvt2bf(t3 - __uint_as_float(h1 & 0xFFFF0000u), t2 - __uint_as_float(h1 << 16));
            uint32_t l2 = cvt2bf(t5 - __uint_as_float(h2 & 0xFFFF0000u), t4 - __uint_as_float(h2 << 16));
            uint32_t l3 = cvt2bf(t7 - __uint_as_float(h3 & 0xFFFF0000u), t6 - __uint_as_float(h3 << 16));
            uint32_t addr = arow + (((uint32_t)(g * 16)) ^ xA);
            sts_v4(sAh + addr, h0, h1, h2, h3);
            sts_v4(sAl + addr, l0, l1, l2, l3);
        }
    }
    __syncthreads();

    // MMA mainloop (conflict-free fragment loads)
    float acc[2][8][4];
#pragma unroll
    for (int mt = 0; mt < 2; mt++)
#pragma unroll
        for (int nt = 0; nt < 8; nt++)
#pragma unroll
            for (int r = 0; r < 4; r++) acc[mt][nt][r] = 0.f;

#pragma unroll
    for (int kt = 0; kt < 4; kt++) {
        uint32_t cb = (uint32_t)(kt * 32 + tq * 4);
        uint32_t ah[2][4], al[2][4];
#pragma unroll
        for (int mt = 0; mt < 2; mt++) {
            int r0 = wid * 32 + mt * 16 + gq;
            uint32_t xr = (uint32_t)(r0 & 7) << 4;   // (r0+8)&7 == r0&7
            uint32_t c0 = cb ^ xr, c1 = (cb + 16) ^ xr;
            uint32_t b0 = (uint32_t)(r0 * 128), b1 = b0 + 1024;
            ah[mt][0] = lds32(sAh + b0 + c0); ah[mt][1] = lds32(sAh + b1 + c0);
            ah[mt][2] = lds32(sAh + b0 + c1); ah[mt][3] = lds32(sAh + b1 + c1);
            al[mt][0] = lds32(sAl + b0 + c0); al[mt][1] = lds32(sAl + b1 + c0);
            al[mt][2] = lds32(sAl + b0 + c1); al[mt][3] = lds32(sAl + b1 + c1);
        }
        uint32_t xb = (uint32_t)gq << 4;
        uint32_t cb0 = cb ^ xb, cb1 = (cb + 16) ^ xb;
#pragma unroll
        for (int nt = 0; nt < 8; nt++) {
            uint32_t rb = (uint32_t)((nt * 8 + gq) * 128);
            uint32_t bh0 = lds32(sBh + rb + cb0), bh1 = lds32(sBh + rb + cb1);
            uint32_t bl0 = lds32(sBl + rb + cb0), bl1 = lds32(sBl + rb + cb1);
#pragma unroll
            for (int mt = 0; mt < 2; mt++) {
                mma16816(acc[mt][nt], ah[mt], bh0, bh1);
                mma16816(acc[mt][nt], ah[mt], bl0, bl1);
                mma16816(acc[mt][nt], al[mt], bh0, bh1);
            }
        }
    }

    // Stage D (fp32, 256B rows, 32B-granule swizzle), reusing A region
    __syncthreads();
    uint32_t sD = base;
#pragma unroll
    for (int mt = 0; mt < 2; mt++) {
        int row0 = wid * 32 + mt * 16 + gq;
        uint32_t xd = (uint32_t)(row0 & 7) << 5;     // (row0+8)&7 == row0&7
        uint32_t rb0 = (uint32_t)(row0 * 256), rb1 = rb0 + 2048;
#pragma unroll
        for (int nt = 0; nt < 8; nt++) {
            uint32_t cby = (uint32_t)((nt * 8 + tq * 2) * 4) ^ xd;
            sts_v2f(sD + rb0 + cby, acc[mt][nt][0], acc[mt][nt][1]);
            sts_v2f(sD + rb1 + cby, acc[mt][nt][2], acc[mt][nt][3]);
        }
    }
    __syncthreads();

    // Column-scan epilogue: thread owns channel c over one 64-edge half.
    int c = tid & 63, halfe = tid >> 6;
    int e0 = halfe * 64;
    float* agg = (PASS == 1) ? g_h1 : g_h2;
    uint32_t cbytes = (uint32_t)c * 4;
    int curd = sDst[e0];
    float mx = ldsf(sD + (uint32_t)(e0 * 256) + (cbytes ^ ((uint32_t)(e0 & 7) << 5)));
#pragma unroll
    for (int k = 1; k < 64; k++) {
        int ee = e0 + k;
        int de = sDst[ee];
        float v = ldsf(sD + (uint32_t)(ee * 256) + (cbytes ^ ((uint32_t)(ee & 7) << 5)));
        if (de != curd) {
            atomMaxF(agg + (size_t)curd * 64 + c, mx);
            curd = de;
            mx = v;
        } else {
            mx = fmaxf(mx, v);
        }
    }
    atomMaxF(agg + (size_t)curd * 64 + c, mx);
}

// ---------- pooling / classifier ----------
__global__ void pool_kernel(const int* __restrict__ batch, const float* __restrict__ bprev) {
    int g = blockIdx.x;
    int lo = 0, hi = NN;
    while (lo < hi) { int m = (lo + hi) >> 1; if (batch[m] < g) lo = m + 1; else hi = m; }
    int start = lo;
    hi = NN;
    while (lo < hi) { int m = (lo + hi) >> 1; if (batch[m] <= g) lo = m + 1; else hi = m; }
    int end = lo;

    int tid = threadIdx.x;
    int k = tid & 63, grp = tid >> 6;
    float bk = __ldg(bprev + k);
    float s = 0.f;
    float mx = -3.0e38f;
    for (int n = start + grp; n < end; n += 4) {
        float z = g_h2[(size_t)n * H + k];
        float v = (__float_as_int(z) == (int)NEG_BITS) ? 0.f : lrelu(z + bk);
        s += v;
        mx = fmaxf(mx, v);
    }
    __shared__ float ss[256], sm[256];
    ss[tid] = s; sm[tid] = mx;
    __syncthreads();
    if (grp == 0) {
        s += ss[64 + k] + ss[128 + k] + ss[192 + k];
        mx = fmaxf(fmaxf(mx, sm[64 + k]), fmaxf(sm[128 + k], sm[192 + k]));
        float cnt = (float)((end - start) > 1 ? (end - start) : 1);
        g_gf[g * 128 + k] = s / cnt;
        g_gf[g * 128 + 64 + k] = (end > start) ? mx : 0.f;
    }
}

__global__ void cls_kernel(const float* __restrict__ Wc1, const float* __restrict__ bc1,
                           const float* __restrict__ Wc2, const float* __restrict__ bc2,
                           float* __restrict__ out) {
    int g = blockIdx.x, t = threadIdx.x;
    __shared__ float gv[128];
    gv[t] = g_gf[g * 128 + t];
    gv[t + 64] = g_gf[g * 128 + 64 + t];
    __syncthreads();
    float acc = __ldg(bc1 + t);
#pragma unroll 8
    for (int j = 0; j < 128; j++) acc = fmaf(gv[j], Wc1[j * 64 + t], acc);
    float v = lrelu(acc) * __ldg(Wc2 + t);
#pragma unroll
    for (int o = 16; o > 0; o >>= 1) v += __shfl_down_sync(0xffffffffu, v, o);
    __shared__ float part[2];
    if ((t & 31) == 0) part[t >> 5] = v;
    __syncthreads();
    if (t == 0) out[g] = part[0] + part[1] + __ldg(bc2);
}

extern "C" void kernel_launch(void* const* d_in, const int* in_sizes, int n_in,
                              void* d_out, int out_size) {
    const float* x    = (const float*)d_in[0];
    const int*   ei   = (const int*)d_in[1];
    const int*   batch= (const int*)d_in[2];
    const float* W1   = (const float*)d_in[3];
    const float* b1   = (const float*)d_in[4];
    const float* W2   = (const float*)d_in[5];
    const float* b2   = (const float*)d_in[6];
    const float* W3   = (const float*)d_in[7];
    const float* b3   = (const float*)d_in[8];
    const float* W4   = (const float*)d_in[9];
    const float* b4   = (const float*)d_in[10];
    const float* Wc1  = (const float*)d_in[11];
    const float* bc1  = (const float*)d_in[12];
    const float* Wc2  = (const float*)d_in[13];
    const float* bc2  = (const float*)d_in[14];
    float* out = (float*)d_out;

    const int* src = ei;
    const int* dst = ei + NE;

    const int DSM = 49664;
    cudaFuncSetAttribute(edge_mma_kernel<1>, cudaFuncAttributeMaxDynamicSharedMemorySize, DSM);
    cudaFuncSetAttribute(edge_mma_kernel<2>, cudaFuncAttributeMaxDynamicSharedMemorySize, DSM);

    const int NB = (NN + 511) / 512;   // 98
    init_kernel<<<(NN * H / 4 + 255) / 256, 256>>>();
    prep_w<<<32, 256>>>(W2, W4);
    hist_kernel<<<(NE + 255) / 256, 256>>>(dst);
    bscan_kernel<<<NB, 512>>>();
    topscan_kernel<<<1, 128>>>(NB);
    addoff_kernel<<<NB, 512>>>();
    scatter_kernel<<<(NE + 255) / 256, 256>>>(src, dst);
    node_mlp6<<<(NN + 127) / 128, 128>>>(x, W1, b1);
    edge_mma_kernel<1><<<NE / 128, 128, DSM>>>();
    node_mlp64<<<(NN + 127) / 128, 128>>>(W3, b3, b2);
    edge_mma_kernel<2><<<NE / 128, 128, DSM>>>();
    pool_kernel<<<NG, 256>>>(batch, b4);
    cls_kernel<<<NG, 64>>>(Wc1, bc1, Wc2, bc2, out);
}

// round 7
// speedup vs baseline: 4.5412x; 1.0895x over previous
#include <cuda_runtime.h>
#include <cuda_bf16.h>
#include <cstdint>

#define NN 50000
#define NE 1280000
#define NG 64
#define H  64
#define NEG_BITS 0xFF800000u

// Scratch (device globals; allocation forbidden)
__device__ float g_h1[NN * H];   // conv1 aggregate (pre-bias, pre-activation max)
__device__ float g_h2[NN * H];   // conv2 aggregate (pre-bias, pre-activation max)
__device__ float g_P[NN * H];
__device__ float g_Q[NN * H];
__device__ int   g_cnt[NN + 1];
__device__ int   g_off[NN + 1];
__device__ int   g_bsum[128];
__device__ int2  g_edge[NE];     // (src,dst) sorted by dst
// Split transposed weights, edge GEMMs: [conv][n(=out)*64 + j(=in)], bf16 hi/lo
__device__ __nv_bfloat16 g_WhT[2][4096];
__device__ __nv_bfloat16 g_WlT[2][4096];
// Split transposed weights, conv2 node GEMM: [n(=out in 0..128)*64 + j], n<64 -> Wd (P), n>=64 -> Wq (Q)
__device__ __nv_bfloat16 g_W3h[8192];
__device__ __nv_bfloat16 g_W3l[8192];
// Pool partials (deterministic slots, no float atomics)
__device__ float g_psum[NG * 4 * 64];
__device__ float g_pmax[NG * 4 * 64];
__device__ int   g_pcnt[NG];

__device__ __forceinline__ float lrelu(float x) { return fmaxf(x, 0.2f * x); }

__device__ __forceinline__ void atomMaxF(float* a, float v) {
    int bi = __float_as_int(v);
    if (bi == (int)0x80000000) bi = 0;
    if (bi >= 0) atomicMax((int*)a, bi);
    else         atomicMin((unsigned int*)a, (unsigned int)bi);
}

__device__ __forceinline__ uint32_t smem_u32(const void* p) {
    uint32_t a;
    asm("{ .reg .u64 t; cvta.to.shared.u64 t, %1; cvt.u32.u64 %0, t; }" : "=r"(a) : "l"(p));
    return a;
}
__device__ __forceinline__ uint32_t lds32(uint32_t a) {
    uint32_t v;
    asm volatile("ld.shared.b32 %0, [%1];" : "=r"(v) : "r"(a));
    return v;
}
__device__ __forceinline__ void sts32(uint32_t a, uint32_t v) {
    asm volatile("st.shared.b32 [%0], %1;" :: "r"(a), "r"(v) : "memory");
}
__device__ __forceinline__ void sts_v4(uint32_t a, uint32_t x, uint32_t y, uint32_t z, uint32_t w) {
    asm volatile("st.shared.v4.b32 [%0], {%1,%2,%3,%4};" :: "r"(a), "r"(x), "r"(y), "r"(z), "r"(w) : "memory");
}
__device__ __forceinline__ void sts_v2f(uint32_t a, float x, float y) {
    asm volatile("st.shared.v2.f32 [%0], {%1,%2};" :: "r"(a), "f"(x), "f"(y) : "memory");
}
__device__ __forceinline__ float ldsf(uint32_t a) {
    float v;
    asm volatile("ld.shared.f32 %0, [%1];" : "=f"(v) : "r"(a));
    return v;
}
__device__ __forceinline__ uint32_t cvt2bf(float hi, float lo) {
    uint32_t r;
    asm("cvt.rn.bf16x2.f32 %0, %1, %2;" : "=r"(r) : "f"(hi), "f"(lo));
    return r;
}

__device__ __forceinline__ void mma16816(float c[4], const uint32_t a[4], uint32_t b0, uint32_t b1) {
    asm volatile(
        "mma.sync.aligned.m16n8k16.row.col.f32.bf16.bf16.f32 "
        "{%0,%1,%2,%3}, {%4,%5,%6,%7}, {%8,%9}, {%0,%1,%2,%3};"
        : "+f"(c[0]), "+f"(c[1]), "+f"(c[2]), "+f"(c[3])
        : "r"(a[0]), "r"(a[1]), "r"(a[2]), "r"(a[3]), "r"(b0), "r"(b1));
}

// ---------- setup kernels ----------
__global__ void init_kernel() {
    int i = blockIdx.x * blockDim.x + threadIdx.x;
    float ni = __int_as_float((int)NEG_BITS);
    float4 v = make_float4(ni, ni, ni, ni);
    if (i < NN * H / 4) {
        ((float4*)g_h1)[i] = v;
        ((float4*)g_h2)[i] = v;
    }
    if (i <= NN) g_cnt[i] = 0;
}

__global__ void prep_w(const float* __restrict__ W2, const float* __restrict__ W4) {
    int i = blockIdx.x * blockDim.x + threadIdx.x;
    if (i >= 8192) return;
    int c = i >> 12, idx = i & 4095;
    const float* W = c ? W4 : W2;
    int n = idx >> 6, j = idx & 63;       // B[n][j] = W[j][n]
    float w = W[j * 64 + n];
    __nv_bfloat16 h = __float2bfloat16_rn(w);
    g_WhT[c][idx] = h;
    g_WlT[c][idx] = __float2bfloat16_rn(w - __bfloat162float(h));
}

// Conv2 node GEMM weights: n<64 -> Wd[j][n] = W3[j][n]-W3[64+j][n]; n>=64 -> W3[64+j][n-64]
__global__ void prep_w3(const float* __restrict__ W3) {
    int i = blockIdx.x * blockDim.x + threadIdx.x;
    if (i >= 8192) return;
    int n = i >> 6, j = i & 63;
    float w;
    if (n < 64) w = W3[j * 64 + n] - W3[(64 + j) * 64 + n];
    else        w = W3[(64 + j) * 64 + (n - 64)];
    __nv_bfloat16 h = __float2bfloat16_rn(w);
    g_W3h[i] = h;
    g_W3l[i] = __float2bfloat16_rn(w - __bfloat162float(h));
}

__global__ void hist_kernel(const int* __restrict__ dst) {
    int e = blockIdx.x * blockDim.x + threadIdx.x;
    if (e < NE) atomicAdd(&g_cnt[dst[e]], 1);
}

__global__ void bscan_kernel() {
    int tid = threadIdx.x;
    int i = blockIdx.x * 512 + tid;
    int v = (i < NN) ? g_cnt[i] : 0;
    int lane = tid & 31, wid = tid >> 5;
    int x = v;
#pragma unroll
    for (int o = 1; o < 32; o <<= 1) {
        int y = __shfl_up_sync(0xffffffffu, x, o);
        if (lane >= o) x += y;
    }
    __shared__ int ws[16];
    if (lane == 31) ws[wid] = x;
    __syncthreads();
    if (wid == 0 && lane < 16) {
        int y = ws[lane];
#pragma unroll
        for (int o = 1; o < 16; o <<= 1) {
            int z = __shfl_up_sync(0xffffu, y, o);
            if (lane >= o) y += z;
        }
        ws[lane] = y;
    }
    __syncthreads();
    int base = wid ? ws[wid - 1] : 0;
    if (i < NN) g_off[i] = base + x - v;
    if (tid == 511) g_bsum[blockIdx.x] = base + x;
}

__global__ void topscan_kernel(int nb) {
    __shared__ int s[128];
    int t = threadIdx.x;
    s[t] = (t < nb) ? g_bsum[t] : 0;
    __syncthreads();
    for (int o = 1; o < 128; o <<= 1) {
        int v = (t >= o) ? s[t - o] : 0;
        __syncthreads();
        s[t] += v;
        __syncthreads();
    }
    if (t < nb) g_bsum[t] = (t == 0) ? 0 : s[t - 1];
}

__global__ void addoff_kernel() {
    int i = blockIdx.x * 512 + threadIdx.x;
    if (i < NN) g_off[i] += g_bsum[i >> 9];
}

__global__ void scatter_kernel(const int* __restrict__ src, const int* __restrict__ dst) {
    int e = blockIdx.x * blockDim.x + threadIdx.x;
    if (e >= NE) return;
    int d = dst[e];
    int pos = atomicAdd(&g_off[d], 1);
    g_edge[pos] = make_int2(src[e], d);
}

// ---------- node MLPs ----------
__global__ __launch_bounds__(128)
void node_mlp6(const float* __restrict__ x, const float* __restrict__ W,
               const float* __restrict__ b) {
    __shared__ float sWd[6 * 64];
    __shared__ float sWq[6 * 64];
    int tid = threadIdx.x;
    for (int i = tid; i < 6 * 64; i += 128) {
        float wb = W[6 * 64 + i];
        sWd[i] = W[i] - wb;
        sWq[i] = wb;
    }
    __syncthreads();
    int n = blockIdx.x * 128 + tid;
    if (n >= NN) return;
    float xr[6];
#pragma unroll
    for (int j = 0; j < 6; j++) xr[j] = x[(size_t)n * 6 + j];
    float* Pp = g_P + (size_t)n * 64;
    float* Qp = g_Q + (size_t)n * 64;
#pragma unroll 4
    for (int k = 0; k < 64; k++) {
        float p = __ldg(b + k), q = 0.f;
#pragma unroll
        for (int j = 0; j < 6; j++) {
            p = fmaf(xr[j], sWd[j * 64 + k], p);
            q = fmaf(xr[j], sWq[j * 64 + k], q);
        }
        Pp[k] = p;
        Qp[k] = q;
    }
}

// Conv2 node GEMM on tensor cores: tile 128 nodes x 128 outputs (P||Q), K=64.
// A = fix_act(g_h1 + b2) split bf16 hi/lo; B = g_W3h/l; D written straight to g_P/g_Q.
// Smem: Ah[0,16K) Al[16K,32K) Bh[32K,48K) Bl[48K,64K)
__global__ __launch_bounds__(128)
void node_mlp64_mma(const float* __restrict__ b3, const float* __restrict__ b2) {
    extern __shared__ char dsm_raw[];
    uint32_t base = smem_u32(dsm_raw);
    uint32_t sAh = base;
    uint32_t sAl = base + 16384;
    uint32_t sBh = base + 32768;
    uint32_t sBl = base + 49152;

    int tid = threadIdx.x;
    int wid = tid >> 5, lane = tid & 31;
    int gq = lane >> 2, tq = lane & 3;

    // Stage B (128 rows x 128B, SW128 swizzle)
    const uint32_t* Bh32 = (const uint32_t*)g_W3h;
    const uint32_t* Bl32 = (const uint32_t*)g_W3l;
#pragma unroll
    for (int it = 0; it < 32; it++) {
        int i = tid + it * 128;            // 4096 u32 per plane
        int n = i >> 5, jc = i & 31;
        uint32_t off = (uint32_t)(n * 128) + (((uint32_t)(jc * 4)) ^ ((uint32_t)(n & 7) << 4));
        sts32(sBh + off, Bh32[i]);
        sts32(sBl + off, Bl32[i]);
    }

    // Build A row (this thread's node)
    int node = blockIdx.x * 128 + tid;
    int cn = node < NN ? node : NN - 1;
    {
        const float4* hr = (const float4*)(g_h1 + (size_t)cn * 64);
        uint32_t arow = (uint32_t)(tid * 128);
        uint32_t xA = (uint32_t)(tid & 7) << 4;
#pragma unroll
        for (int g = 0; g < 8; g++) {
            float4 v0 = hr[2 * g], v1 = hr[2 * g + 1];
            float t[8];
            float* vp0 = &v0.x;
            float* vp1 = &v1.x;
#pragma unroll
            for (int kk = 0; kk < 4; kk++) {
                float z0 = vp0[kk];
                t[kk] = (__float_as_int(z0) == (int)NEG_BITS) ? 0.f : lrelu(z0 + __ldg(b2 + 8 * g + kk));
                float z1 = vp1[kk];
                t[4 + kk] = (__float_as_int(z1) == (int)NEG_BITS) ? 0.f : lrelu(z1 + __ldg(b2 + 8 * g + 4 + kk));
            }
            uint32_t h0 = cvt2bf(t[1], t[0]), h1 = cvt2bf(t[3], t[2]);
            uint32_t h2 = cvt2bf(t[5], t[4]), h3 = cvt2bf(t[7], t[6]);
            uint32_t l0 = cvt2bf(t[1] - __uint_as_float(h0 & 0xFFFF0000u), t[0] - __uint_as_float(h0 << 16));
            uint32_t l1 = cvt2bf(t[3] - __uint_as_float(h1 & 0xFFFF0000u), t[2] - __uint_as_float(h1 << 16));
            uint32_t l2 = cvt2bf(t[5] - __uint_as_float(h2 & 0xFFFF0000u), t[4] - __uint_as_float(h2 << 16));
            uint32_t l3 = cvt2bf(t[7] - __uint_as_float(h3 & 0xFFFF0000u), t[6] - __uint_as_float(h3 << 16));
            uint32_t addr = arow + (((uint32_t)(g * 16)) ^ xA);
            sts_v4(sAh + addr, h0, h1, h2, h3);
            sts_v4(sAl + addr, l0, l1, l2, l3);
        }
    }
    __syncthreads();

    // Accumulators: [mt][nt][4], bias init on P half (cols < 64)
    float acc[2][16][4];
#pragma unroll
    for (int nt = 0; nt < 16; nt++) {
        int col = nt * 8 + tq * 2;
        float b0 = 0.f, b1 = 0.f;
        if (col < 64) { b0 = __ldg(b3 + col); b1 = __ldg(b3 + col + 1); }
#pragma unroll
        for (int mt = 0; mt < 2; mt++) {
            acc[mt][nt][0] = b0; acc[mt][nt][1] = b1;
            acc[mt][nt][2] = b0; acc[mt][nt][3] = b1;
        }
    }

#pragma unroll
    for (int kt = 0; kt < 4; kt++) {
        uint32_t cb = (uint32_t)(kt * 32 + tq * 4);
        uint32_t ah[2][4], al[2][4];
#pragma unroll
        for (int mt = 0; mt < 2; mt++) {
            int r0 = wid * 32 + mt * 16 + gq;
            uint32_t xr = (uint32_t)(r0 & 7) << 4;
            uint32_t c0 = cb ^ xr, c1 = (cb + 16) ^ xr;
            uint32_t b0 = (uint32_t)(r0 * 128), b1 = b0 + 1024;
            ah[mt][0] = lds32(sAh + b0 + c0); ah[mt][1] = lds32(sAh + b1 + c0);
            ah[mt][2] = lds32(sAh + b0 + c1); ah[mt][3] = lds32(sAh + b1 + c1);
            al[mt][0] = lds32(sAl + b0 + c0); al[mt][1] = lds32(sAl + b1 + c0);
            al[mt][2] = lds32(sAl + b0 + c1); al[mt][3] = lds32(sAl + b1 + c1);
        }
        uint32_t xb = (uint32_t)gq << 4;
        uint32_t cb0 = cb ^ xb, cb1 = (cb + 16) ^ xb;
#pragma unroll
        for (int nt = 0; nt < 16; nt++) {
            uint32_t rb = (uint32_t)((nt * 8 + gq) * 128);
            uint32_t bh0 = lds32(sBh + rb + cb0), bh1 = lds32(sBh + rb + cb1);
            uint32_t bl0 = lds32(sBl + rb + cb0), bl1 = lds32(sBl + rb + cb1);
#pragma unroll
            for (int mt = 0; mt < 2; mt++) {
                mma16816(acc[mt][nt], ah[mt], bh0, bh1);
                mma16816(acc[mt][nt], ah[mt], bl0, bl1);
                mma16816(acc[mt][nt], al[mt], bh0, bh1);
            }
        }
    }

    // Direct global writes (8B per fragment half)
    int tilebase = blockIdx.x * 128;
#pragma unroll
    for (int mt = 0; mt < 2; mt++) {
        int r0 = wid * 32 + mt * 16 + gq;
        int n0 = tilebase + r0, n1 = n0 + 8;
#pragma unroll
        for (int nt = 0; nt < 16; nt++) {
            int col = nt * 8 + tq * 2;
            float* basep = (col < 64) ? g_P : g_Q;
            int c = col & 63;
            if (n0 < NN)
                *(float2*)(basep + (size_t)n0 * 64 + c) = make_float2(acc[mt][nt][0], acc[mt][nt][1]);
            if (n1 < NN)
                *(float2*)(basep + (size_t)n1 * 64 + c) = make_float2(acc[mt][nt][2], acc[mt][nt][3]);
        }
    }
}

// ---------- mma.sync edge kernel (unchanged core, int2 edges) ----------
template <int PASS>
__global__ __launch_bounds__(128, 4)
void edge_mma_kernel() {
    extern __shared__ char dsm_raw[];
    uint32_t base = smem_u32(dsm_raw);
    uint32_t sAh = base;
    uint32_t sAl = base + 16384;
    uint32_t sBh = base + 32768;
    uint32_t sBl = base + 40960;
    int* sDst = (int*)(dsm_raw + 49152);

    int tid = threadIdx.x;
    int wid = tid >> 5, lane = tid & 31;
    int gq = lane >> 2, tq = lane & 3;

    const uint32_t* Bh32 = (const uint32_t*)g_WhT[PASS - 1];
    const uint32_t* Bl32 = (const uint32_t*)g_WlT[PASS - 1];
#pragma unroll
    for (int it = 0; it < 16; it++) {
        int i = tid + it * 128;
        int n = i >> 5, jc = i & 31;
        uint32_t off = (uint32_t)(n * 128) + (((uint32_t)(jc * 4)) ^ ((uint32_t)(n & 7) << 4));
        sts32(sBh + off, Bh32[i]);
        sts32(sBl + off, Bl32[i]);
    }

    int e = blockIdx.x * 128 + tid;
    int2 sd = g_edge[e];
    int s = sd.x, d = sd.y;
    sDst[tid] = d;
    {
        const float4* Pp = (const float4*)(g_P + (size_t)d * 64);
        const float4* Qp = (const float4*)(g_Q + (size_t)s * 64);
        uint32_t arow = (uint32_t)(tid * 128);
        uint32_t xA = (uint32_t)(tid & 7) << 4;
#pragma unroll
        for (int g = 0; g < 8; g++) {
            float4 a0 = Pp[2 * g],     c0 = Qp[2 * g];
            float4 a1 = Pp[2 * g + 1], c1 = Qp[2 * g + 1];
            float t0 = lrelu(a0.x + c0.x), t1 = lrelu(a0.y + c0.y);
            float t2 = lrelu(a0.z + c0.z), t3 = lrelu(a0.w + c0.w);
            float t4 = lrelu(a1.x + c1.x), t5 = lrelu(a1.y + c1.y);
            float t6 = lrelu(a1.z + c1.z), t7 = lrelu(a1.w + c1.w);
            uint32_t h0 = cvt2bf(t1, t0), h1 = cvt2bf(t3, t2);
            uint32_t h2 = cvt2bf(t5, t4), h3 = cvt2bf(t7, t6);
            uint32_t l0 = cvt2bf(t1 - __uint_as_float(h0 & 0xFFFF0000u), t0 - __uint_as_float(h0 << 16));
            uint32_t l1 = cvt2bf(t3 - __uint_as_float(h1 & 0xFFFF0000u), t2 - __uint_as_float(h1 << 16));
            uint32_t l2 = cvt2bf(t5 - __uint_as_float(h2 & 0xFFFF0000u), t4 - __uint_as_float(h2 << 16));
            uint32_t l3 = cvt2bf(t7 - __uint_as_float(h3 & 0xFFFF0000u), t6 - __uint_as_float(h3 << 16));
            uint32_t addr = arow + (((uint32_t)(g * 16)) ^ xA);
            sts_v4(sAh + addr, h0, h1, h2, h3);
            sts_v4(sAl + addr, l0, l1, l2, l3);
        }
    }
    __syncthreads();

    float acc[2][8][4];
#pragma unroll
    for (int mt = 0; mt < 2; mt++)
#pragma unroll
        for (int nt = 0; nt < 8; nt++)
#pragma unroll
            for (int r = 0; r < 4; r++) acc[mt][nt][r] = 0.f;

#pragma unroll
    for (int kt = 0; kt < 4; kt++) {
        uint32_t cb = (uint32_t)(kt * 32 + tq * 4);
        uint32_t ah[2][4], al[2][4];
#pragma unroll
        for (int mt = 0; mt < 2; mt++) {
            int r0 = wid * 32 + mt * 16 + gq;
            uint32_t xr = (uint32_t)(r0 & 7) << 4;
            uint32_t c0 = cb ^ xr, c1 = (cb + 16) ^ xr;
            uint32_t b0 = (uint32_t)(r0 * 128), b1 = b0 + 1024;
            ah[mt][0] = lds32(sAh + b0 + c0); ah[mt][1] = lds32(sAh + b1 + c0);
            ah[mt][2] = lds32(sAh + b0 + c1); ah[mt][3] = lds32(sAh + b1 + c1);
            al[mt][0] = lds32(sAl + b0 + c0); al[mt][1] = lds32(sAl + b1 + c0);
            al[mt][2] = lds32(sAl + b0 + c1); al[mt][3] = lds32(sAl + b1 + c1);
        }
        uint32_t xb = (uint32_t)gq << 4;
        uint32_t cb0 = cb ^ xb, cb1 = (cb + 16) ^ xb;
#pragma unroll
        for (int nt = 0; nt < 8; nt++) {
            uint32_t rb = (uint32_t)((nt * 8 + gq) * 128);
            uint32_t bh0 = lds32(sBh + rb + cb0), bh1 = lds32(sBh + rb + cb1);
            uint32_t bl0 = lds32(sBl + rb + cb0), bl1 = lds32(sBl + rb + cb1);
#pragma unroll
            for (int mt = 0; mt < 2; mt++) {
                mma16816(acc[mt][nt], ah[mt], bh0, bh1);
                mma16816(acc[mt][nt], ah[mt], bl0, bl1);
                mma16816(acc[mt][nt], al[mt], bh0, bh1);
            }
        }
    }

    __syncthreads();
    uint32_t sD = base;
#pragma unroll
    for (int mt = 0; mt < 2; mt++) {
        int row0 = wid * 32 + mt * 16 + gq;
        uint32_t xd = (uint32_t)(row0 & 7) << 5;
        uint32_t rb0 = (uint32_t)(row0 * 256), rb1 = rb0 + 2048;
#pragma unroll
        for (int nt = 0; nt < 8; nt++) {
            uint32_t cby = (uint32_t)((nt * 8 + tq * 2) * 4) ^ xd;
            sts_v2f(sD + rb0 + cby, acc[mt][nt][0], acc[mt][nt][1]);
            sts_v2f(sD + rb1 + cby, acc[mt][nt][2], acc[mt][nt][3]);
        }
    }
    __syncthreads();

    int c = tid & 63, halfe = tid >> 6;
    int e0 = halfe * 64;
    float* agg = (PASS == 1) ? g_h1 : g_h2;
    uint32_t cbytes = (uint32_t)c * 4;
    int curd = sDst[e0];
    float mx = ldsf(sD + (uint32_t)(e0 * 256) + (cbytes ^ ((uint32_t)(e0 & 7) << 5)));
#pragma unroll
    for (int k = 1; k < 64; k++) {
        int ee = e0 + k;
        int de = sDst[ee];
        float v = ldsf(sD + (uint32_t)(ee * 256) + (cbytes ^ ((uint32_t)(ee & 7) << 5)));
        if (de != curd) {
            atomMaxF(agg + (size_t)curd * 64 + c, mx);
            curd = de;
            mx = v;
        } else {
            mx = fmaxf(mx, v);
        }
    }
    atomMaxF(agg + (size_t)curd * 64 + c, mx);
}

// ---------- pooling / classifier ----------
// grid (NG, 4): quarter-ranges, deterministic partial slots.
__global__ void pool_kernel(const int* __restrict__ batch, const float* __restrict__ bprev) {
    int g = blockIdx.x, q = blockIdx.y;
    int lo = 0, hi = NN;
    while (lo < hi) { int m = (lo + hi) >> 1; if (batch[m] < g) lo = m + 1; else hi = m; }
    int start = lo;
    hi = NN;
    while (lo < hi) { int m = (lo + hi) >> 1; if (batch[m] <= g) lo = m + 1; else hi = m; }
    int end = lo;
    int len = end - start;
    int qs = start + (len * q) / 4;
    int qe = start + (len * (q + 1)) / 4;

    int tid = threadIdx.x;
    int k = tid & 63, grp = tid >> 6;
    float bk = __ldg(bprev + k);
    float s = 0.f;
    float mx = -3.0e38f;
    for (int n = qs + grp; n < qe; n += 4) {
        float z = g_h2[(size_t)n * H + k];
        float v = (__float_as_int(z) == (int)NEG_BITS) ? 0.f : lrelu(z + bk);
        s += v;
        mx = fmaxf(mx, v);
    }
    __shared__ float ss[256], sm[256];
    ss[tid] = s; sm[tid] = mx;
    __syncthreads();
    if (grp == 0) {
        s += ss[64 + k] + ss[128 + k] + ss[192 + k];
        mx = fmaxf(fmaxf(mx, sm[64 + k]), fmaxf(sm[128 + k], sm[192 + k]));
        g_psum[(g * 4 + q) * 64 + k] = s;
        g_pmax[(g * 4 + q) * 64 + k] = mx;
    }
    if (q == 0 && tid == 0) g_pcnt[g] = len;
}

__global__ void cls_kernel(const float* __restrict__ Wc1, const float* __restrict__ bc1,
                           const float* __restrict__ Wc2, const float* __restrict__ bc2,
                           float* __restrict__ out) {
    int g = blockIdx.x, t = threadIdx.x;
    __shared__ float gv[128];
    int cnt = g_pcnt[g];
    {
        float s = g_psum[(g * 4 + 0) * 64 + t] + g_psum[(g * 4 + 1) * 64 + t]
                + g_psum[(g * 4 + 2) * 64 + t] + g_psum[(g * 4 + 3) * 64 + t];
        float m = fmaxf(fmaxf(g_pmax[(g * 4 + 0) * 64 + t], g_pmax[(g * 4 + 1) * 64 + t]),
                        fmaxf(g_pmax[(g * 4 + 2) * 64 + t], g_pmax[(g * 4 + 3) * 64 + t]));
        gv[t] = s / (float)(cnt > 1 ? cnt : 1);
        gv[t + 64] = (cnt > 0) ? m : 0.f;
    }
    __syncthreads();
    float acc = __ldg(bc1 + t);
#pragma unroll 8
    for (int j = 0; j < 128; j++) acc = fmaf(gv[j], Wc1[j * 64 + t], acc);
    float v = lrelu(acc) * __ldg(Wc2 + t);
#pragma unroll
    for (int o = 16; o > 0; o >>= 1) v += __shfl_down_sync(0xffffffffu, v, o);
    __shared__ float part[2];
    if ((t & 31) == 0) part[t >> 5] = v;
    __syncthreads();
    if (t == 0) out[g] = part[0] + part[1] + __ldg(bc2);
}

extern "C" void kernel_launch(void* const* d_in, const int* in_sizes, int n_in,
                              void* d_out, int out_size) {
    const float* x    = (const float*)d_in[0];
    const int*   ei   = (const int*)d_in[1];
    const int*   batch= (const int*)d_in[2];
    const float* W1   = (const float*)d_in[3];
    const float* b1   = (const float*)d_in[4];
    const float* W2   = (const float*)d_in[5];
    const float* b2   = (const float*)d_in[6];
    const float* W3   = (const float*)d_in[7];
    const float* b3   = (const float*)d_in[8];
    const float* W4   = (const float*)d_in[9];
    const float* b4   = (const float*)d_in[10];
    const float* Wc1  = (const float*)d_in[11];
    const float* bc1  = (const float*)d_in[12];
    const float* Wc2  = (const float*)d_in[13];
    const float* bc2  = (const float*)d_in[14];
    float* out = (float*)d_out;

    const int* src = ei;
    const int* dst = ei + NE;

    const int DSM_E = 49664;
    const int DSM_N = 65536;
    cudaFuncSetAttribute(edge_mma_kernel<1>, cudaFuncAttributeMaxDynamicSharedMemorySize, DSM_E);
    cudaFuncSetAttribute(edge_mma_kernel<2>, cudaFuncAttributeMaxDynamicSharedMemorySize, DSM_E);
    cudaFuncSetAttribute(node_mlp64_mma, cudaFuncAttributeMaxDynamicSharedMemorySize, DSM_N);

    const int NB = (NN + 511) / 512;   // 98
    init_kernel<<<(NN * H / 4 + 255) / 256, 256>>>();
    prep_w<<<32, 256>>>(W2, W4);
    prep_w3<<<32, 256>>>(W3);
    hist_kernel<<<(NE + 255) / 256, 256>>>(dst);
    bscan_kernel<<<NB, 512>>>();
    topscan_kernel<<<1, 128>>>(NB);
    addoff_kernel<<<NB, 512>>>();
    scatter_kernel<<<(NE + 255) / 256, 256>>>(src, dst);
    node_mlp6<<<(NN + 127) / 128, 128>>>(x, W1, b1);
    edge_mma_kernel<1><<<NE / 128, 128, DSM_E>>>();
    node_mlp64_mma<<<(NN + 127) / 128, 128, DSM_N>>>(b3, b2);
    edge_mma_kernel<2><<<NE / 128, 128, DSM_E>>>();
    pool_kernel<<<dim3(NG, 4), 256>>>(batch, b4);
    cls_kernel<<<NG, 64>>>(Wc1, bc1, Wc2, bc2, out);
}

// round 8
// speedup vs baseline: 4.5778x; 1.0081x over previous
#include <cuda_runtime.h>
#include <cuda_bf16.h>
#include <cstdint>

#define NN 50000
#define NE 1280000
#define NG 64
#define H  64
#define NEG_BITS 0xFF800000u

// Scratch (device globals; allocation forbidden)
__device__ float g_h1[NN * H];
__device__ float g_h2[NN * H];
__device__ float g_P[NN * H];
__device__ float g_Q[NN * H];
__device__ int   g_cnt[NN + 1];
__device__ int   g_off[NN + 1];
__device__ int   g_bsum[128];
__device__ int2  g_edge[NE];
__device__ __nv_bfloat16 g_WhT[2][4096];
__device__ __nv_bfloat16 g_WlT[2][4096];
__device__ __nv_bfloat16 g_W3h[8192];
__device__ __nv_bfloat16 g_W3l[8192];
__device__ float g_psum[NG * 4 * 64];
__device__ float g_pmax[NG * 4 * 64];
__device__ int   g_pcnt[NG];

__device__ __forceinline__ float lrelu(float x) { return fmaxf(x, 0.2f * x); }

__device__ __forceinline__ void atomMaxF(float* a, float v) {
    int bi = __float_as_int(v);
    if (bi == (int)0x80000000) bi = 0;
    if (bi >= 0) atomicMax((int*)a, bi);
    else         atomicMin((unsigned int*)a, (unsigned int)bi);
}

__device__ __forceinline__ uint32_t smem_u32(const void* p) {
    uint32_t a;
    asm("{ .reg .u64 t; cvta.to.shared.u64 t, %1; cvt.u32.u64 %0, t; }" : "=r"(a) : "l"(p));
    return a;
}
__device__ __forceinline__ uint32_t lds32(uint32_t a) {
    uint32_t v;
    asm volatile("ld.shared.b32 %0, [%1];" : "=r"(v) : "r"(a));
    return v;
}
__device__ __forceinline__ void sts32(uint32_t a, uint32_t v) {
    asm volatile("st.shared.b32 [%0], %1;" :: "r"(a), "r"(v) : "memory");
}
__device__ __forceinline__ void sts_v4(uint32_t a, uint32_t x, uint32_t y, uint32_t z, uint32_t w) {
    asm volatile("st.shared.v4.b32 [%0], {%1,%2,%3,%4};" :: "r"(a), "r"(x), "r"(y), "r"(z), "r"(w) : "memory");
}
__device__ __forceinline__ void sts_v2f(uint32_t a, float x, float y) {
    asm volatile("st.shared.v2.f32 [%0], {%1,%2};" :: "r"(a), "f"(x), "f"(y) : "memory");
}
__device__ __forceinline__ float ldsf(uint32_t a) {
    float v;
    asm volatile("ld.shared.f32 %0, [%1];" : "=f"(v) : "r"(a));
    return v;
}
__device__ __forceinline__ uint32_t cvt2bf(float hi, float lo) {
    uint32_t r;
    asm("cvt.rn.bf16x2.f32 %0, %1, %2;" : "=r"(r) : "f"(hi), "f"(lo));
    return r;
}

__device__ __forceinline__ void mma16816(float c[4], const uint32_t a[4], uint32_t b0, uint32_t b1) {
    asm volatile(
        "mma.sync.aligned.m16n8k16.row.col.f32.bf16.bf16.f32 "
        "{%0,%1,%2,%3}, {%4,%5,%6,%7}, {%8,%9}, {%0,%1,%2,%3};"
        : "+f"(c[0]), "+f"(c[1]), "+f"(c[2]), "+f"(c[3])
        : "r"(a[0]), "r"(a[1]), "r"(a[2]), "r"(a[3]), "r"(b0), "r"(b1));
}

// ---------- fused setup: init buffers + both weight preps ----------
// blocks [0,3125): init; [3125,3157): prep edge W; [3157,3189): prep node W3
__global__ void setup_kernel(const float* __restrict__ W2, const float* __restrict__ W4,
                             const float* __restrict__ W3) {
    int blk = blockIdx.x;
    if (blk < 3125) {
        int i = blk * 256 + threadIdx.x;
        float ni = __int_as_float((int)NEG_BITS);
        float4 v = make_float4(ni, ni, ni, ni);
        if (i < NN * H / 4) {
            ((float4*)g_h1)[i] = v;
            ((float4*)g_h2)[i] = v;
        }
        if (i <= NN) g_cnt[i] = 0;
    } else if (blk < 3157) {
        int i = (blk - 3125) * 256 + threadIdx.x;   // 0..8191
        int c = i >> 12, idx = i & 4095;
        const float* W = c ? W4 : W2;
        int n = idx >> 6, j = idx & 63;
        float w = W[j * 64 + n];
        __nv_bfloat16 h = __float2bfloat16_rn(w);
        g_WhT[c][idx] = h;
        g_WlT[c][idx] = __float2bfloat16_rn(w - __bfloat162float(h));
    } else {
        int i = (blk - 3157) * 256 + threadIdx.x;   // 0..8191
        int n = i >> 6, j = i & 63;
        float w;
        if (n < 64) w = W3[j * 64 + n] - W3[(64 + j) * 64 + n];
        else        w = W3[(64 + j) * 64 + (n - 64)];
        __nv_bfloat16 h = __float2bfloat16_rn(w);
        g_W3h[i] = h;
        g_W3l[i] = __float2bfloat16_rn(w - __bfloat162float(h));
    }
}

__global__ void hist_kernel(const int* __restrict__ dst) {
    int e = blockIdx.x * blockDim.x + threadIdx.x;
    if (e < NE) atomicAdd(&g_cnt[dst[e]], 1);
}

__global__ void bscan_kernel() {
    int tid = threadIdx.x;
    int i = blockIdx.x * 512 + tid;
    int v = (i < NN) ? g_cnt[i] : 0;
    int lane = tid & 31, wid = tid >> 5;
    int x = v;
#pragma unroll
    for (int o = 1; o < 32; o <<= 1) {
        int y = __shfl_up_sync(0xffffffffu, x, o);
        if (lane >= o) x += y;
    }
    __shared__ int ws[16];
    if (lane == 31) ws[wid] = x;
    __syncthreads();
    if (wid == 0 && lane < 16) {
        int y = ws[lane];
#pragma unroll
        for (int o = 1; o < 16; o <<= 1) {
            int z = __shfl_up_sync(0xffffu, y, o);
            if (lane >= o) y += z;
        }
        ws[lane] = y;
    }
    __syncthreads();
    int base = wid ? ws[wid - 1] : 0;
    if (i < NN) g_off[i] = base + x - v;
    if (tid == 511) g_bsum[blockIdx.x] = base + x;
}

__global__ void topscan_kernel(int nb) {
    __shared__ int s[128];
    int t = threadIdx.x;
    s[t] = (t < nb) ? g_bsum[t] : 0;
    __syncthreads();
    for (int o = 1; o < 128; o <<= 1) {
        int v = (t >= o) ? s[t - o] : 0;
        __syncthreads();
        s[t] += v;
        __syncthreads();
    }
    if (t < nb) g_bsum[t] = (t == 0) ? 0 : s[t - 1];
}

// scatter with fused block-base add (g_off holds block-local offsets)
__global__ void scatter_kernel(const int* __restrict__ src, const int* __restrict__ dst) {
    int e = blockIdx.x * blockDim.x + threadIdx.x;
    if (e >= NE) return;
    int d = dst[e];
    int pos = atomicAdd(&g_off[d], 1) + g_bsum[d >> 9];
    g_edge[pos] = make_int2(src[e], d);
}

// ---------- node MLPs ----------
__global__ __launch_bounds__(128)
void node_mlp6(const float* __restrict__ x, const float* __restrict__ W,
               const float* __restrict__ b) {
    __shared__ float sWd[6 * 64];
    __shared__ float sWq[6 * 64];
    int tid = threadIdx.x;
    for (int i = tid; i < 6 * 64; i += 128) {
        float wb = W[6 * 64 + i];
        sWd[i] = W[i] - wb;
        sWq[i] = wb;
    }
    __syncthreads();
    int n = blockIdx.x * 128 + tid;
    if (n >= NN) return;
    float xr[6];
#pragma unroll
    for (int j = 0; j < 6; j++) xr[j] = x[(size_t)n * 6 + j];
    float* Pp = g_P + (size_t)n * 64;
    float* Qp = g_Q + (size_t)n * 64;
#pragma unroll 4
    for (int k = 0; k < 64; k++) {
        float p = __ldg(b + k), q = 0.f;
#pragma unroll
        for (int j = 0; j < 6; j++) {
            p = fmaf(xr[j], sWd[j * 64 + k], p);
            q = fmaf(xr[j], sWq[j * 64 + k], q);
        }
        Pp[k] = p;
        Qp[k] = q;
    }
}

// Conv2 node GEMM on tensor cores (unchanged from R7)
__global__ __launch_bounds__(128)
void node_mlp64_mma(const float* __restrict__ b3, const float* __restrict__ b2) {
    extern __shared__ char dsm_raw[];
    uint32_t base = smem_u32(dsm_raw);
    uint32_t sAh = base;
    uint32_t sAl = base + 16384;
    uint32_t sBh = base + 32768;
    uint32_t sBl = base + 49152;

    int tid = threadIdx.x;
    int wid = tid >> 5, lane = tid & 31;
    int gq = lane >> 2, tq = lane & 3;

    const uint32_t* Bh32 = (const uint32_t*)g_W3h;
    const uint32_t* Bl32 = (const uint32_t*)g_W3l;
#pragma unroll
    for (int it = 0; it < 32; it++) {
        int i = tid + it * 128;
        int n = i >> 5, jc = i & 31;
        uint32_t off = (uint32_t)(n * 128) + (((uint32_t)(jc * 4)) ^ ((uint32_t)(n & 7) << 4));
        sts32(sBh + off, Bh32[i]);
        sts32(sBl + off, Bl32[i]);
    }

    int node = blockIdx.x * 128 + tid;
    int cn = node < NN ? node : NN - 1;
    {
        const float4* hr = (const float4*)(g_h1 + (size_t)cn * 64);
        uint32_t arow = (uint32_t)(tid * 128);
        uint32_t xA = (uint32_t)(tid & 7) << 4;
#pragma unroll
        for (int g = 0; g < 8; g++) {
            float4 v0 = hr[2 * g], v1 = hr[2 * g + 1];
            float t[8];
            float* vp0 = &v0.x;
            float* vp1 = &v1.x;
#pragma unroll
            for (int kk = 0; kk < 4; kk++) {
                float z0 = vp0[kk];
                t[kk] = (__float_as_int(z0) == (int)NEG_BITS) ? 0.f : lrelu(z0 + __ldg(b2 + 8 * g + kk));
                float z1 = vp1[kk];
                t[4 + kk] = (__float_as_int(z1) == (int)NEG_BITS) ? 0.f : lrelu(z1 + __ldg(b2 + 8 * g + 4 + kk));
            }
            uint32_t h0 = cvt2bf(t[1], t[0]), h1 = cvt2bf(t[3], t[2]);
            uint32_t h2 = cvt2bf(t[5], t[4]), h3 = cvt2bf(t[7], t[6]);
            uint32_t l0 = cvt2bf(t[1] - __uint_as_float(h0 & 0xFFFF0000u), t[0] - __uint_as_float(h0 << 16));
            uint32_t l1 = cvt2bf(t[3] - __uint_as_float(h1 & 0xFFFF0000u), t[2] - __uint_as_float(h1 << 16));
            uint32_t l2 = cvt2bf(t[5] - __uint_as_float(h2 & 0xFFFF0000u), t[4] - __uint_as_float(h2 << 16));
            uint32_t l3 = cvt2bf(t[7] - __uint_as_float(h3 & 0xFFFF0000u), t[6] - __uint_as_float(h3 << 16));
            uint32_t addr = arow + (((uint32_t)(g * 16)) ^ xA);
            sts_v4(sAh + addr, h0, h1, h2, h3);
            sts_v4(sAl + addr, l0, l1, l2, l3);
        }
    }
    __syncthreads();

    float acc[2][16][4];
#pragma unroll
    for (int nt = 0; nt < 16; nt++) {
        int col = nt * 8 + tq * 2;
        float b0 = 0.f, b1 = 0.f;
        if (col < 64) { b0 = __ldg(b3 + col); b1 = __ldg(b3 + col + 1); }
#pragma unroll
        for (int mt = 0; mt < 2; mt++) {
            acc[mt][nt][0] = b0; acc[mt][nt][1] = b1;
            acc[mt][nt][2] = b0; acc[mt][nt][3] = b1;
        }
    }

#pragma unroll
    for (int kt = 0; kt < 4; kt++) {
        uint32_t cb = (uint32_t)(kt * 32 + tq * 4);
        uint32_t ah[2][4], al[2][4];
#pragma unroll
        for (int mt = 0; mt < 2; mt++) {
            int r0 = wid * 32 + mt * 16 + gq;
            uint32_t xr = (uint32_t)(r0 & 7) << 4;
            uint32_t c0 = cb ^ xr, c1 = (cb + 16) ^ xr;
            uint32_t b0 = (uint32_t)(r0 * 128), b1 = b0 + 1024;
            ah[mt][0] = lds32(sAh + b0 + c0); ah[mt][1] = lds32(sAh + b1 + c0);
            ah[mt][2] = lds32(sAh + b0 + c1); ah[mt][3] = lds32(sAh + b1 + c1);
            al[mt][0] = lds32(sAl + b0 + c0); al[mt][1] = lds32(sAl + b1 + c0);
            al[mt][2] = lds32(sAl + b0 + c1); al[mt][3] = lds32(sAl + b1 + c1);
        }
        uint32_t xb = (uint32_t)gq << 4;
        uint32_t cb0 = cb ^ xb, cb1 = (cb + 16) ^ xb;
#pragma unroll
        for (int nt = 0; nt < 16; nt++) {
            uint32_t rb = (uint32_t)((nt * 8 + gq) * 128);
            uint32_t bh0 = lds32(sBh + rb + cb0), bh1 = lds32(sBh + rb + cb1);
            uint32_t bl0 = lds32(sBl + rb + cb0), bl1 = lds32(sBl + rb + cb1);
#pragma unroll
            for (int mt = 0; mt < 2; mt++) {
                mma16816(acc[mt][nt], ah[mt], bh0, bh1);
                mma16816(acc[mt][nt], ah[mt], bl0, bl1);
                mma16816(acc[mt][nt], al[mt], bh0, bh1);
            }
        }
    }

    int tilebase = blockIdx.x * 128;
#pragma unroll
    for (int mt = 0; mt < 2; mt++) {
        int r0 = wid * 32 + mt * 16 + gq;
        int n0 = tilebase + r0, n1 = n0 + 8;
#pragma unroll
        for (int nt = 0; nt < 16; nt++) {
            int col = nt * 8 + tq * 2;
            float* basep = (col < 64) ? g_P : g_Q;
            int c = col & 63;
            if (n0 < NN)
                *(float2*)(basep + (size_t)n0 * 64 + c) = make_float2(acc[mt][nt][0], acc[mt][nt][1]);
            if (n1 < NN)
                *(float2*)(basep + (size_t)n1 * 64 + c) = make_float2(acc[mt][nt][2], acc[mt][nt][3]);
        }
    }
}

// ---------- mma.sync edge kernel: 256-edge tiles, 8 warps ----------
// Smem: Ah[0,32K) Al[32K,64K) Bh[64K,72K) Bl[72K,80K) sDst[80K,81K)
// D (fp32, 256 rows x 256B swizzled) reuses [0,64K).
template <int PASS>
__global__ __launch_bounds__(256, 2)
void edge_mma_kernel() {
    extern __shared__ char dsm_raw[];
    uint32_t base = smem_u32(dsm_raw);
    uint32_t sAh = base;
    uint32_t sAl = base + 32768;
    uint32_t sBh = base + 65536;
    uint32_t sBl = base + 73728;
    int* sDst = (int*)(dsm_raw + 81920);

    int tid = threadIdx.x;
    int wid = tid >> 5, lane = tid & 31;
    int gq = lane >> 2, tq = lane & 3;

    const uint32_t* Bh32 = (const uint32_t*)g_WhT[PASS - 1];
    const uint32_t* Bl32 = (const uint32_t*)g_WlT[PASS - 1];
#pragma unroll
    for (int it = 0; it < 8; it++) {
        int i = tid + it * 256;            // 2048 u32 per plane
        int n = i >> 5, jc = i & 31;
        uint32_t off = (uint32_t)(n * 128) + (((uint32_t)(jc * 4)) ^ ((uint32_t)(n & 7) << 4));
        sts32(sBh + off, Bh32[i]);
        sts32(sBl + off, Bl32[i]);
    }

    int e = blockIdx.x * 256 + tid;        // NE % 256 == 0
    int2 sd = g_edge[e];
    int s = sd.x, d = sd.y;
    sDst[tid] = d;
    {
        const float4* Pp = (const float4*)(g_P + (size_t)d * 64);
        const float4* Qp = (const float4*)(g_Q + (size_t)s * 64);
        uint32_t arow = (uint32_t)(tid * 128);
        uint32_t xA = (uint32_t)(tid & 7) << 4;
#pragma unroll
        for (int g = 0; g < 8; g++) {
            float4 a0 = Pp[2 * g],     c0 = Qp[2 * g];
            float4 a1 = Pp[2 * g + 1], c1 = Qp[2 * g + 1];
            float t0 = lrelu(a0.x + c0.x), t1 = lrelu(a0.y + c0.y);
            float t2 = lrelu(a0.z + c0.z), t3 = lrelu(a0.w + c0.w);
            float t4 = lrelu(a1.x + c1.x), t5 = lrelu(a1.y + c1.y);
            float t6 = lrelu(a1.z + c1.z), t7 = lrelu(a1.w + c1.w);
            uint32_t h0 = cvt2bf(t1, t0), h1 = cvt2bf(t3, t2);
            uint32_t h2 = cvt2bf(t5, t4), h3 = cvt2bf(t7, t6);
            uint32_t l0 = cvt2bf(t1 - __uint_as_float(h0 & 0xFFFF0000u), t0 - __uint_as_float(h0 << 16));
            uint32_t l1 = cvt2bf(t3 - __uint_as_float(h1 & 0xFFFF0000u), t2 - __uint_as_float(h1 << 16));
            uint32_t l2 = cvt2bf(t5 - __uint_as_float(h2 & 0xFFFF0000u), t4 - __uint_as_float(h2 << 16));
            uint32_t l3 = cvt2bf(t7 - __uint_as_float(h3 & 0xFFFF0000u), t6 - __uint_as_float(h3 << 16));
            uint32_t addr = arow + (((uint32_t)(g * 16)) ^ xA);
            sts_v4(sAh + addr, h0, h1, h2, h3);
            sts_v4(sAl + addr, l0, l1, l2, l3);
        }
    }
    __syncthreads();

    float acc[2][8][4];
#pragma unroll
    for (int mt = 0; mt < 2; mt++)
#pragma unroll
        for (int nt = 0; nt < 8; nt++)
#pragma unroll
            for (int r = 0; r < 4; r++) acc[mt][nt][r] = 0.f;

#pragma unroll
    for (int kt = 0; kt < 4; kt++) {
        uint32_t cb = (uint32_t)(kt * 32 + tq * 4);
        uint32_t ah[2][4], al[2][4];
#pragma unroll
        for (int mt = 0; mt < 2; mt++) {
            int r0 = wid * 32 + mt * 16 + gq;
            uint32_t xr = (uint32_t)(r0 & 7) << 4;
            uint32_t c0 = cb ^ xr, c1 = (cb + 16) ^ xr;
            uint32_t b0 = (uint32_t)(r0 * 128), b1 = b0 + 1024;
            ah[mt][0] = lds32(sAh + b0 + c0); ah[mt][1] = lds32(sAh + b1 + c0);
            ah[mt][2] = lds32(sAh + b0 + c1); ah[mt][3] = lds32(sAh + b1 + c1);
            al[mt][0] = lds32(sAl + b0 + c0); al[mt][1] = lds32(sAl + b1 + c0);
            al[mt][2] = lds32(sAl + b0 + c1); al[mt][3] = lds32(sAl + b1 + c1);
        }
        uint32_t xb = (uint32_t)gq << 4;
        uint32_t cb0 = cb ^ xb, cb1 = (cb + 16) ^ xb;
#pragma unroll
        for (int nt = 0; nt < 8; nt++) {
            uint32_t rb = (uint32_t)((nt * 8 + gq) * 128);
            uint32_t bh0 = lds32(sBh + rb + cb0), bh1 = lds32(sBh + rb + cb1);
            uint32_t bl0 = lds32(sBl + rb + cb0), bl1 = lds32(sBl + rb + cb1);
#pragma unroll
            for (int mt = 0; mt < 2; mt++) {
                mma16816(acc[mt][nt], ah[mt], bh0, bh1);
                mma16816(acc[mt][nt], ah[mt], bl0, bl1);
                mma16816(acc[mt][nt], al[mt], bh0, bh1);
            }
        }
    }

    __syncthreads();
    uint32_t sD = base;
#pragma unroll
    for (int mt = 0; mt < 2; mt++) {
        int row0 = wid * 32 + mt * 16 + gq;
        uint32_t xd = (uint32_t)(row0 & 7) << 5;
        uint32_t rb0 = (uint32_t)(row0 * 256), rb1 = rb0 + 2048;
#pragma unroll
        for (int nt = 0; nt < 8; nt++) {
            uint32_t cby = (uint32_t)((nt * 8 + tq * 2) * 4) ^ xd;
            sts_v2f(sD + rb0 + cby, acc[mt][nt][0], acc[mt][nt][1]);
            sts_v2f(sD + rb1 + cby, acc[mt][nt][2], acc[mt][nt][3]);
        }
    }
    __syncthreads();

    // Column-scan epilogue: thread owns channel c over one 64-edge quarter.
    int c = tid & 63, quarter = tid >> 6;
    int e0 = quarter * 64;
    float* agg = (PASS == 1) ? g_h1 : g_h2;
    uint32_t cbytes = (uint32_t)c * 4;
    int curd = sDst[e0];
    float mx = ldsf(sD + (uint32_t)(e0 * 256) + (cbytes ^ ((uint32_t)(e0 & 7) << 5)));
#pragma unroll
    for (int k = 1; k < 64; k++) {
        int ee = e0 + k;
        int de = sDst[ee];
        float v = ldsf(sD + (uint32_t)(ee * 256) + (cbytes ^ ((uint32_t)(ee & 7) << 5)));
        if (de != curd) {
            atomMaxF(agg + (size_t)curd * 64 + c, mx);
            curd = de;
            mx = v;
        } else {
            mx = fmaxf(mx, v);
        }
    }
    atomMaxF(agg + (size_t)curd * 64 + c, mx);
}

// ---------- pooling / classifier ----------
__global__ void pool_kernel(const int* __restrict__ batch, const float* __restrict__ bprev) {
    int g = blockIdx.x, q = blockIdx.y;
    int lo = 0, hi = NN;
    while (lo < hi) { int m = (lo + hi) >> 1; if (batch[m] < g) lo = m + 1; else hi = m; }
    int start = lo;
    hi = NN;
    while (lo < hi) { int m = (lo + hi) >> 1; if (batch[m] <= g) lo = m + 1; else hi = m; }
    int end = lo;
    int len = end - start;
    int qs = start + (len * q) / 4;
    int qe = start + (len * (q + 1)) / 4;

    int tid = threadIdx.x;
    int k = tid & 63, grp = tid >> 6;
    float bk = __ldg(bprev + k);
    float s = 0.f;
    float mx = -3.0e38f;
    for (int n = qs + grp; n < qe; n += 4) {
        float z = g_h2[(size_t)n * H + k];
        float v = (__float_as_int(z) == (int)NEG_BITS) ? 0.f : lrelu(z + bk);
        s += v;
        mx = fmaxf(mx, v);
    }
    __shared__ float ss[256], sm[256];
    ss[tid] = s; sm[tid] = mx;
    __syncthreads();
    if (grp == 0) {
        s += ss[64 + k] + ss[128 + k] + ss[192 + k];
        mx = fmaxf(fmaxf(mx, sm[64 + k]), fmaxf(sm[128 + k], sm[192 + k]));
        g_psum[(g * 4 + q) * 64 + k] = s;
        g_pmax[(g * 4 + q) * 64 + k] = mx;
    }
    if (q == 0 && tid == 0) g_pcnt[g] = len;
}

__global__ void cls_kernel(const float* __restrict__ Wc1, const float* __restrict__ bc1,
                           const float* __restrict__ Wc2, const float* __restrict__ bc2,
                           float* __restrict__ out) {
    int g = blockIdx.x, t = threadIdx.x;
    __shared__ float gv[128];
    int cnt = g_pcnt[g];
    {
        float s = g_psum[(g * 4 + 0) * 64 + t] + g_psum[(g * 4 + 1) * 64 + t]
                + g_psum[(g * 4 + 2) * 64 + t] + g_psum[(g * 4 + 3) * 64 + t];
        float m = fmaxf(fmaxf(g_pmax[(g * 4 + 0) * 64 + t], g_pmax[(g * 4 + 1) * 64 + t]),
                        fmaxf(g_pmax[(g * 4 + 2) * 64 + t], g_pmax[(g * 4 + 3) * 64 + t]));
        gv[t] = s / (float)(cnt > 1 ? cnt : 1);
        gv[t + 64] = (cnt > 0) ? m : 0.f;
    }
    __syncthreads();
    float acc = __ldg(bc1 + t);
#pragma unroll 8
    for (int j = 0; j < 128; j++) acc = fmaf(gv[j], Wc1[j * 64 + t], acc);
    float v = lrelu(acc) * __ldg(Wc2 + t);
#pragma unroll
    for (int o = 16; o > 0; o >>= 1) v += __shfl_down_sync(0xffffffffu, v, o);
    __shared__ float part[2];
    if ((t & 31) == 0) part[t >> 5] = v;
    __syncthreads();
    if (t == 0) out[g] = part[0] + part[1] + __ldg(bc2);
}

extern "C" void kernel_launch(void* const* d_in, const int* in_sizes, int n_in,
                              void* d_out, int out_size) {
    const float* x    = (const float*)d_in[0];
    const int*   ei   = (const int*)d_in[1];
    const int*   batch= (const int*)d_in[2];
    const float* W1   = (const float*)d_in[3];
    const float* b1   = (const float*)d_in[4];
    const float* W2   = (const float*)d_in[5];
    const float* b2   = (const float*)d_in[6];
    const float* W3   = (const float*)d_in[7];
    const float* b3   = (const float*)d_in[8];
    const float* W4   = (const float*)d_in[9];
    const float* b4   = (const float*)d_in[10];
    const float* Wc1  = (const float*)d_in[11];
    const float* bc1  = (const float*)d_in[12];
    const float* Wc2  = (const float*)d_in[13];
    const float* bc2  = (const float*)d_in[14];
    float* out = (float*)d_out;

    const int* src = ei;
    const int* dst = ei + NE;

    const int DSM_E = 82944;   // A 64K + B 16K + dst 1K
    const int DSM_N = 65536;
    cudaFuncSetAttribute(edge_mma_kernel<1>, cudaFuncAttributeMaxDynamicSharedMemorySize, DSM_E);
    cudaFuncSetAttribute(edge_mma_kernel<2>, cudaFuncAttributeMaxDynamicSharedMemorySize, DSM_E);
    cudaFuncSetAttribute(node_mlp64_mma, cudaFuncAttributeMaxDynamicSharedMemorySize, DSM_N);

    const int NB = (NN + 511) / 512;   // 98
    setup_kernel<<<3189, 256>>>(W2, W4, W3);
    hist_kernel<<<(NE + 255) / 256, 256>>>(dst);
    bscan_kernel<<<NB, 512>>>();
    topscan_kernel<<<1, 128>>>(NB);
    scatter_kernel<<<(NE + 255) / 256, 256>>>(src, dst);
    node_mlp6<<<(NN + 127) / 128, 128>>>(x, W1, b1);
    edge_mma_kernel<1><<<NE / 256, 256, DSM_E>>>();
    node_mlp64_mma<<<(NN + 127) / 128, 128, DSM_N>>>(b3, b2);
    edge_mma_kernel<2><<<NE / 256, 256, DSM_E>>>();
    pool_kernel<<<dim3(NG, 4), 256>>>(batch, b4);
    cls_kernel<<<NG, 64>>>(Wc1, bc1, Wc2, bc2, out);
}

// round 10
// speedup vs baseline: 5.1962x; 1.1351x over previous
#include <cuda_runtime.h>
#include <cuda_bf16.h>
#include <cstdint>

#define NN 50000
#define NE 1280000
#define NG 64
#define H  64
#define NEG_BITS 0xFF800000u

// Scratch (device globals; allocation forbidden)
__device__ float g_h1[NN * H];
__device__ float g_h2[NN * H];
__device__ float g_P[NN * H];
__device__ float g_Q[NN * H];
__device__ int   g_cnt[NN + 1];
__device__ int   g_off[NN + 1];
__device__ int   g_bsum[128];
__device__ int2  g_edge[NE];
__device__ __nv_bfloat16 g_WhT[2][4096];
__device__ __nv_bfloat16 g_WlT[2][4096];
__device__ __nv_bfloat16 g_W3h[8192];
__device__ __nv_bfloat16 g_W3l[8192];
__device__ float g_psum[NG * 4 * 64];
__device__ float g_pmax[NG * 4 * 64];
__device__ int   g_pcnt[NG];

__device__ __forceinline__ float lrelu(float x) { return fmaxf(x, 0.2f * x); }

__device__ __forceinline__ void atomMaxF(float* a, float v) {
    int bi = __float_as_int(v);
    if (bi == (int)0x80000000) bi = 0;
    if (bi >= 0) atomicMax((int*)a, bi);
    else         atomicMin((unsigned int*)a, (unsigned int)bi);
}

__device__ __forceinline__ uint32_t smem_u32(const void* p) {
    uint32_t a;
    asm("{ .reg .u64 t; cvta.to.shared.u64 t, %1; cvt.u32.u64 %0, t; }" : "=r"(a) : "l"(p));
    return a;
}
__device__ __forceinline__ uint32_t lds32(uint32_t a) {
    uint32_t v;
    asm volatile("ld.shared.b32 %0, [%1];" : "=r"(v) : "r"(a));
    return v;
}
__device__ __forceinline__ void sts32(uint32_t a, uint32_t v) {
    asm volatile("st.shared.b32 [%0], %1;" :: "r"(a), "r"(v) : "memory");
}
__device__ __forceinline__ void sts_v4(uint32_t a, uint32_t x, uint32_t y, uint32_t z, uint32_t w) {
    asm volatile("st.shared.v4.b32 [%0], {%1,%2,%3,%4};" :: "r"(a), "r"(x), "r"(y), "r"(z), "r"(w) : "memory");
}
__device__ __forceinline__ void sts_v2f(uint32_t a, float x, float y) {
    asm volatile("st.shared.v2.f32 [%0], {%1,%2};" :: "r"(a), "f"(x), "f"(y) : "memory");
}
__device__ __forceinline__ float2 lds_v2f(uint32_t a) {
    float2 v;
    asm volatile("ld.shared.v2.f32 {%0,%1}, [%2];" : "=f"(v.x), "=f"(v.y) : "r"(a));
    return v;
}
__device__ __forceinline__ uint32_t cvt2bf(float hi, float lo) {
    uint32_t r;
    asm("cvt.rn.bf16x2.f32 %0, %1, %2;" : "=r"(r) : "f"(hi), "f"(lo));
    return r;
}
__device__ __forceinline__ void ldsm_x4(uint32_t r[4], uint32_t addr) {
    asm volatile("ldmatrix.sync.aligned.m8n8.x4.shared.b16 {%0,%1,%2,%3}, [%4];"
        : "=r"(r[0]), "=r"(r[1]), "=r"(r[2]), "=r"(r[3]) : "r"(addr));
}

__device__ __forceinline__ void mma16816(float c[4], const uint32_t a[4], uint32_t b0, uint32_t b1) {
    asm volatile(
        "mma.sync.aligned.m16n8k16.row.col.f32.bf16.bf16.f32 "
        "{%0,%1,%2,%3}, {%4,%5,%6,%7}, {%8,%9}, {%0,%1,%2,%3};"
        : "+f"(c[0]), "+f"(c[1]), "+f"(c[2]), "+f"(c[3])
        : "r"(a[0]), "r"(a[1]), "r"(a[2]), "r"(a[3]), "r"(b0), "r"(b1));
}

// ---------- fused setup ----------
__global__ void setup_kernel(const float* __restrict__ W2, const float* __restrict__ W4,
                             const float* __restrict__ W3) {
    int blk = blockIdx.x;
    if (blk < 3125) {
        int i = blk * 256 + threadIdx.x;
        float ni = __int_as_float((int)NEG_BITS);
        float4 v = make_float4(ni, ni, ni, ni);
        if (i < NN * H / 4) {
            ((float4*)g_h1)[i] = v;
            ((float4*)g_h2)[i] = v;
        }
        if (i <= NN) g_cnt[i] = 0;
    } else if (blk < 3157) {
        int i = (blk - 3125) * 256 + threadIdx.x;
        int c = i >> 12, idx = i & 4095;
        const float* W = c ? W4 : W2;
        int n = idx >> 6, j = idx & 63;
        float w = W[j * 64 + n];
        __nv_bfloat16 h = __float2bfloat16_rn(w);
        g_WhT[c][idx] = h;
        g_WlT[c][idx] = __float2bfloat16_rn(w - __bfloat162float(h));
    } else {
        int i = (blk - 3157) * 256 + threadIdx.x;
        int n = i >> 6, j = i & 63;
        float w;
        if (n < 64) w = W3[j * 64 + n] - W3[(64 + j) * 64 + n];
        else        w = W3[(64 + j) * 64 + (n - 64)];
        __nv_bfloat16 h = __float2bfloat16_rn(w);
        g_W3h[i] = h;
        g_W3l[i] = __float2bfloat16_rn(w - __bfloat162float(h));
    }
}

__global__ void hist_kernel(const int* __restrict__ dst) {
    int e = blockIdx.x * blockDim.x + threadIdx.x;
    if (e < NE) atomicAdd(&g_cnt[dst[e]], 1);
}

__global__ void bscan_kernel() {
    int tid = threadIdx.x;
    int i = blockIdx.x * 512 + tid;
    int v = (i < NN) ? g_cnt[i] : 0;
    int lane = tid & 31, wid = tid >> 5;
    int x = v;
#pragma unroll
    for (int o = 1; o < 32; o <<= 1) {
        int y = __shfl_up_sync(0xffffffffu, x, o);
        if (lane >= o) x += y;
    }
    __shared__ int ws[16];
    if (lane == 31) ws[wid] = x;
    __syncthreads();
    if (wid == 0 && lane < 16) {
        int y = ws[lane];
#pragma unroll
        for (int o = 1; o < 16; o <<= 1) {
            int z = __shfl_up_sync(0xffffu, y, o);
            if (lane >= o) y += z;
        }
        ws[lane] = y;
    }
    __syncthreads();
    int base = wid ? ws[wid - 1] : 0;
    if (i < NN) g_off[i] = base + x - v;
    if (tid == 511) g_bsum[blockIdx.x] = base + x;
}

__global__ void topscan_kernel(int nb) {
    __shared__ int s[128];
    int t = threadIdx.x;
    s[t] = (t < nb) ? g_bsum[t] : 0;
    __syncthreads();
    for (int o = 1; o < 128; o <<= 1) {
        int v = (t >= o) ? s[t - o] : 0;
        __syncthreads();
        s[t] += v;
        __syncthreads();
    }
    if (t < nb) g_bsum[t] = (t == 0) ? 0 : s[t - 1];
}

__global__ void scatter_kernel(const int* __restrict__ src, const int* __restrict__ dst) {
    int e = blockIdx.x * blockDim.x + threadIdx.x;
    if (e >= NE) return;
    int d = dst[e];
    int pos = atomicAdd(&g_off[d], 1) + g_bsum[d >> 9];
    g_edge[pos] = make_int2(src[e], d);
}

// ---------- node MLPs ----------
__global__ __launch_bounds__(128)
void node_mlp6(const float* __restrict__ x, const float* __restrict__ W,
               const float* __restrict__ b) {
    __shared__ float sWd[6 * 64];
    __shared__ float sWq[6 * 64];
    int tid = threadIdx.x;
    for (int i = tid; i < 6 * 64; i += 128) {
        float wb = W[6 * 64 + i];
        sWd[i] = W[i] - wb;
        sWq[i] = wb;
    }
    __syncthreads();
    int n = blockIdx.x * 128 + tid;
    if (n >= NN) return;
    float xr[6];
#pragma unroll
    for (int j = 0; j < 6; j++) xr[j] = x[(size_t)n * 6 + j];
    float* Pp = g_P + (size_t)n * 64;
    float* Qp = g_Q + (size_t)n * 64;
#pragma unroll 4
    for (int k = 0; k < 64; k++) {
        float p = __ldg(b + k), q = 0.f;
#pragma unroll
        for (int j = 0; j < 6; j++) {
            p = fmaf(xr[j], sWd[j * 64 + k], p);
            q = fmaf(xr[j], sWq[j * 64 + k], q);
        }
        Pp[k] = p;
        Qp[k] = q;
    }
}

// Conv2 node GEMM on tensor cores (unchanged)
__global__ __launch_bounds__(128)
void node_mlp64_mma(const float* __restrict__ b3, const float* __restrict__ b2) {
    extern __shared__ char dsm_raw[];
    uint32_t base = smem_u32(dsm_raw);
    uint32_t sAh = base;
    uint32_t sAl = base + 16384;
    uint32_t sBh = base + 32768;
    uint32_t sBl = base + 49152;

    int tid = threadIdx.x;
    int wid = tid >> 5, lane = tid & 31;
    int gq = lane >> 2, tq = lane & 3;

    const uint32_t* Bh32 = (const uint32_t*)g_W3h;
    const uint32_t* Bl32 = (const uint32_t*)g_W3l;
#pragma unroll
    for (int it = 0; it < 32; it++) {
        int i = tid + it * 128;
        int n = i >> 5, jc = i & 31;
        uint32_t off = (uint32_t)(n * 128) + (((uint32_t)(jc * 4)) ^ ((uint32_t)(n & 7) << 4));
        sts32(sBh + off, Bh32[i]);
        sts32(sBl + off, Bl32[i]);
    }

    int node = blockIdx.x * 128 + tid;
    int cn = node < NN ? node : NN - 1;
    {
        const float4* hr = (const float4*)(g_h1 + (size_t)cn * 64);
        uint32_t arow = (uint32_t)(tid * 128);
        uint32_t xA = (uint32_t)(tid & 7) << 4;
#pragma unroll
        for (int g = 0; g < 8; g++) {
            float4 v0 = hr[2 * g], v1 = hr[2 * g + 1];
            float t[8];
            float* vp0 = &v0.x;
            float* vp1 = &v1.x;
#pragma unroll
            for (int kk = 0; kk < 4; kk++) {
                float z0 = vp0[kk];
                t[kk] = (__float_as_int(z0) == (int)NEG_BITS) ? 0.f : lrelu(z0 + __ldg(b2 + 8 * g + kk));
                float z1 = vp1[kk];
                t[4 + kk] = (__float_as_int(z1) == (int)NEG_BITS) ? 0.f : lrelu(z1 + __ldg(b2 + 8 * g + 4 + kk));
            }
            uint32_t h0 = cvt2bf(t[1], t[0]), h1 = cvt2bf(t[3], t[2]);
            uint32_t h2 = cvt2bf(t[5], t[4]), h3 = cvt2bf(t[7], t[6]);
            uint32_t l0 = cvt2bf(t[1] - __uint_as_float(h0 & 0xFFFF0000u), t[0] - __uint_as_float(h0 << 16));
            uint32_t l1 = cvt2bf(t[3] - __uint_as_float(h1 & 0xFFFF0000u), t[2] - __uint_as_float(h1 << 16));
            uint32_t l2 = cvt2bf(t[5] - __uint_as_float(h2 & 0xFFFF0000u), t[4] - __uint_as_float(h2 << 16));
            uint32_t l3 = cvt2bf(t[7] - __uint_as_float(h3 & 0xFFFF0000u), t[6] - __uint_as_float(h3 << 16));
            uint32_t addr = arow + (((uint32_t)(g * 16)) ^ xA);
            sts_v4(sAh + addr, h0, h1, h2, h3);
            sts_v4(sAl + addr, l0, l1, l2, l3);
        }
    }
    __syncthreads();

    float acc[2][16][4];
#pragma unroll
    for (int nt = 0; nt < 16; nt++) {
        int col = nt * 8 + tq * 2;
        float b0 = 0.f, b1 = 0.f;
        if (col < 64) { b0 = __ldg(b3 + col); b1 = __ldg(b3 + col + 1); }
#pragma unroll
        for (int mt = 0; mt < 2; mt++) {
            acc[mt][nt][0] = b0; acc[mt][nt][1] = b1;
            acc[mt][nt][2] = b0; acc[mt][nt][3] = b1;
        }
    }

#pragma unroll
    for (int kt = 0; kt < 4; kt++) {
        uint32_t cb = (uint32_t)(kt * 32 + tq * 4);
        uint32_t ah[2][4], al[2][4];
#pragma unroll
        for (int mt = 0; mt < 2; mt++) {
            int r0 = wid * 32 + mt * 16 + gq;
            uint32_t xr = (uint32_t)(r0 & 7) << 4;
            uint32_t c0 = cb ^ xr, c1 = (cb + 16) ^ xr;
            uint32_t b0 = (uint32_t)(r0 * 128), b1 = b0 + 1024;
            ah[mt][0] = lds32(sAh + b0 + c0); ah[mt][1] = lds32(sAh + b1 + c0);
            ah[mt][2] = lds32(sAh + b0 + c1); ah[mt][3] = lds32(sAh + b1 + c1);
            al[mt][0] = lds32(sAl + b0 + c0); al[mt][1] = lds32(sAl + b1 + c0);
            al[mt][2] = lds32(sAl + b0 + c1); al[mt][3] = lds32(sAl + b1 + c1);
        }
        uint32_t xb = (uint32_t)gq << 4;
        uint32_t cb0 = cb ^ xb, cb1 = (cb + 16) ^ xb;
#pragma unroll
        for (int nt = 0; nt < 16; nt++) {
            uint32_t rb = (uint32_t)((nt * 8 + gq) * 128);
            uint32_t bh0 = lds32(sBh + rb + cb0), bh1 = lds32(sBh + rb + cb1);
            uint32_t bl0 = lds32(sBl + rb + cb0), bl1 = lds32(sBl + rb + cb1);
#pragma unroll
            for (int mt = 0; mt < 2; mt++) {
                mma16816(acc[mt][nt], ah[mt], bh0, bh1);
                mma16816(acc[mt][nt], ah[mt], bl0, bl1);
                mma16816(acc[mt][nt], al[mt], bh0, bh1);
            }
        }
    }

    int tilebase = blockIdx.x * 128;
#pragma unroll
    for (int mt = 0; mt < 2; mt++) {
        int r0 = wid * 32 + mt * 16 + gq;
        int n0 = tilebase + r0, n1 = n0 + 8;
#pragma unroll
        for (int nt = 0; nt < 16; nt++) {
            int col = nt * 8 + tq * 2;
            float* basep = (col < 64) ? g_P : g_Q;
            int c = col & 63;
            if (n0 < NN)
                *(float2*)(basep + (size_t)n0 * 64 + c) = make_float2(acc[mt][nt][0], acc[mt][nt][1]);
            if (n1 < NN)
                *(float2*)(basep + (size_t)n1 * 64 + c) = make_float2(acc[mt][nt][2], acc[mt][nt][3]);
        }
    }
}

// ---------- mma.sync edge kernel: 256-edge tiles, ldmatrix mainloop ----------
// Smem: Ah[0,32K) Al[32K,64K) Bh[64K,72K) Bl[72K,80K) sDst[80K,81K)
// D (fp32, 256 rows x 256B swizzled) reuses [0,64K).
template <int PASS>
__global__ __launch_bounds__(256, 2)
void edge_mma_kernel() {
    extern __shared__ char dsm_raw[];
    uint32_t base = smem_u32(dsm_raw);
    uint32_t sAh = base;
    uint32_t sAl = base + 32768;
    uint32_t sBh = base + 65536;
    uint32_t sBl = base + 73728;
    int* sDst = (int*)(dsm_raw + 81920);

    int tid = threadIdx.x;
    int wid = tid >> 5, lane = tid & 31;
    int tq = lane & 3;

    const uint32_t* Bh32 = (const uint32_t*)g_WhT[PASS - 1];
    const uint32_t* Bl32 = (const uint32_t*)g_WlT[PASS - 1];
#pragma unroll
    for (int it = 0; it < 8; it++) {
        int i = tid + it * 256;
        int n = i >> 5, jc = i & 31;
        uint32_t off = (uint32_t)(n * 128) + (((uint32_t)(jc * 4)) ^ ((uint32_t)(n & 7) << 4));
        sts32(sBh + off, Bh32[i]);
        sts32(sBl + off, Bl32[i]);
    }

    int e = blockIdx.x * 256 + tid;        // NE % 256 == 0
    int2 sd = g_edge[e];
    int s = sd.x, d = sd.y;
    sDst[tid] = d;
    {
        const float4* Pp = (const float4*)(g_P + (size_t)d * 64);
        const float4* Qp = (const float4*)(g_Q + (size_t)s * 64);
        uint32_t arow = (uint32_t)(tid * 128);
        uint32_t xA = (uint32_t)(tid & 7) << 4;
#pragma unroll
        for (int g = 0; g < 8; g++) {
            float4 a0 = Pp[2 * g],     c0 = Qp[2 * g];
            float4 a1 = Pp[2 * g + 1], c1 = Qp[2 * g + 1];
            float t0 = lrelu(a0.x + c0.x), t1 = lrelu(a0.y + c0.y);
            float t2 = lrelu(a0.z + c0.z), t3 = lrelu(a0.w + c0.w);
            float t4 = lrelu(a1.x + c1.x), t5 = lrelu(a1.y + c1.y);
            float t6 = lrelu(a1.z + c1.z), t7 = lrelu(a1.w + c1.w);
            uint32_t h0 = cvt2bf(t1, t0), h1 = cvt2bf(t3, t2);
            uint32_t h2 = cvt2bf(t5, t4), h3 = cvt2bf(t7, t6);
            uint32_t l0 = cvt2bf(t1 - __uint_as_float(h0 & 0xFFFF0000u), t0 - __uint_as_float(h0 << 16));
            uint32_t l1 = cvt2bf(t3 - __uint_as_float(h1 & 0xFFFF0000u), t2 - __uint_as_float(h1 << 16));
            uint32_t l2 = cvt2bf(t5 - __uint_as_float(h2 & 0xFFFF0000u), t4 - __uint_as_float(h2 << 16));
            uint32_t l3 = cvt2bf(t7 - __uint_as_float(h3 & 0xFFFF0000u), t6 - __uint_as_float(h3 << 16));
            uint32_t addr = arow + (((uint32_t)(g * 16)) ^ xA);
            sts_v4(sAh + addr, h0, h1, h2, h3);
            sts_v4(sAl + addr, l0, l1, l2, l3);
        }
    }
    __syncthreads();

    float acc[2][8][4];
#pragma unroll
    for (int mt = 0; mt < 2; mt++)
#pragma unroll
        for (int nt = 0; nt < 8; nt++)
#pragma unroll
            for (int r = 0; r < 4; r++) acc[mt][nt][r] = 0.f;

    // ldmatrix lane geometry: mface = which 8x8 matrix this lane addresses
    int l8 = lane & 7, mface = lane >> 3;       // mface 0..3
    uint32_t colp = (uint32_t)(mface >> 1) * 16;  // +16B for k-upper matrices
    int rsel = (mface & 1) * 8 + l8;             // row-within-16 for this lane
    // A addresses (per mt): row = wid*32 + mt*16 + rsel
    uint32_t aBase[2], aX[2];
#pragma unroll
    for (int mt = 0; mt < 2; mt++) {
        int r = wid * 32 + mt * 16 + rsel;
        aBase[mt] = (uint32_t)(r * 128);
        aX[mt] = (uint32_t)(r & 7) << 4;
    }
    // B addresses (per nt-pair p): n = p*16 + rsel
    uint32_t bBase[4], bX[4];
#pragma unroll
    for (int p = 0; p < 4; p++) {
        int n = p * 16 + rsel;
        bBase[p] = (uint32_t)(n * 128);
        bX[p] = (uint32_t)(n & 7) << 4;
    }

#pragma unroll
    for (int kt = 0; kt < 4; kt++) {
        uint32_t kb = (uint32_t)(kt * 32) + colp;
        uint32_t ah[2][4], al[2][4];
#pragma unroll
        for (int mt = 0; mt < 2; mt++) {
            uint32_t off = kb ^ aX[mt];
            ldsm_x4(ah[mt], sAh + aBase[mt] + off);
            ldsm_x4(al[mt], sAl + aBase[mt] + off);
        }
#pragma unroll
        for (int p = 0; p < 4; p++) {
            uint32_t off = kb ^ bX[p];
            uint32_t bh[4], bl[4];
            ldsm_x4(bh, sBh + bBase[p] + off);
            ldsm_x4(bl, sBl + bBase[p] + off);
            // bh = {nt=2p:b0, nt=2p+1:b0, nt=2p:b1, nt=2p+1:b1}
#pragma unroll
            for (int mt = 0; mt < 2; mt++) {
                mma16816(acc[mt][2 * p],     ah[mt], bh[0], bh[2]);
                mma16816(acc[mt][2 * p],     ah[mt], bl[0], bl[2]);
                mma16816(acc[mt][2 * p],     al[mt], bh[0], bh[2]);
                mma16816(acc[mt][2 * p + 1], ah[mt], bh[1], bh[3]);
                mma16816(acc[mt][2 * p + 1], ah[mt], bl[1], bl[3]);
                mma16816(acc[mt][2 * p + 1], al[mt], bh[1], bh[3]);
            }
        }
    }

    __syncthreads();
    uint32_t sD = base;
    int gq = lane >> 2;
#pragma unroll
    for (int mt = 0; mt < 2; mt++) {
        int row0 = wid * 32 + mt * 16 + gq;
        uint32_t xd = (uint32_t)(row0 & 7) << 5;
        uint32_t rb0 = (uint32_t)(row0 * 256), rb1 = rb0 + 2048;
#pragma unroll
        for (int nt = 0; nt < 8; nt++) {
            uint32_t cby = (uint32_t)((nt * 8 + tq * 2) * 4) ^ xd;
            sts_v2f(sD + rb0 + cby, acc[mt][nt][0], acc[mt][nt][1]);
            sts_v2f(sD + rb1 + cby, acc[mt][nt][2], acc[mt][nt][3]);
        }
    }
    __syncthreads();

    // float2 column-scan epilogue: thread owns channel pair (2cp,2cp+1) over a 32-edge segment
    int cp = tid & 31, seg = tid >> 5;
    int e0 = seg * 32;
    float* agg = (PASS == 1) ? g_h1 : g_h2;
    uint32_t cb2 = (uint32_t)cp * 8;
    int curd = sDst[e0];
    float2 mx = lds_v2f(sD + (uint32_t)(e0 * 256) + (cb2 ^ ((uint32_t)(e0 & 7) << 5)));
#pragma unroll
    for (int k = 1; k < 32; k++) {
        int ee = e0 + k;
        int de = sDst[ee];
        float2 v = lds_v2f(sD + (uint32_t)(ee * 256) + (cb2 ^ ((uint32_t)(ee & 7) << 5)));
        if (de != curd) {
            atomMaxF(agg + (size_t)curd * 64 + 2 * cp, mx.x);
            atomMaxF(agg + (size_t)curd * 64 + 2 * cp + 1, mx.y);
            curd = de;
            mx = v;
        } else {
            mx.x = fmaxf(mx.x, v.x);
            mx.y = fmaxf(mx.y, v.y);
        }
    }
    atomMaxF(agg + (size_t)curd * 64 + 2 * cp, mx.x);
    atomMaxF(agg + (size_t)curd * 64 + 2 * cp + 1, mx.y);
}

// ---------- pooling / classifier ----------
__global__ void pool_kernel(const int* __restrict__ batch, const float* __restrict__ bprev) {
    int g = blockIdx.x, q = blockIdx.y;
    int lo = 0, hi = NN;
    while (lo < hi) { int m = (lo + hi) >> 1; if (batch[m] < g) lo = m + 1; else hi = m; }
    int start = lo;
    hi = NN;
    while (lo < hi) { int m = (lo + hi) >> 1; if (batch[m] <= g) lo = m + 1; else hi = m; }
    int end = lo;
    int len = end - start;
    int qs = start + (len * q) / 4;
    int qe = start + (len * (q + 1)) / 4;

    int tid = threadIdx.x;
    int k = tid & 63, grp = tid >> 6;
    float bk = __ldg(bprev + k);
    float s = 0.f;
    float mx = -3.0e38f;
    for (int n = qs + grp; n < qe; n += 4) {
        float z = g_h2[(size_t)n * H + k];
        float v = (__float_as_int(z) == (int)NEG_BITS) ? 0.f : lrelu(z + bk);
        s += v;
        mx = fmaxf(mx, v);
    }
    __shared__ float ss[256], sm[256];
    ss[tid] = s; sm[tid] = mx;
    __syncthreads();
    if (grp == 0) {
        s += ss[64 + k] + ss[128 + k] + ss[192 + k];
        mx = fmaxf(fmaxf(mx, sm[64 + k]), fmaxf(sm[128 + k], sm[192 + k]));
        g_psum[(g * 4 + q) * 64 + k] = s;
        g_pmax[(g * 4 + q) * 64 + k] = mx;
    }
    if (q == 0 && tid == 0) g_pcnt[g] = len;
}

__global__ void cls_kernel(const float* __restrict__ Wc1, const float* __restrict__ bc1,
                           const float* __restrict__ Wc2, const float* __restrict__ bc2,
                           float* __restrict__ out) {
    int g = blockIdx.x, t = threadIdx.x;
    __shared__ float gv[128];
    int cnt = g_pcnt[g];
    {
        float s = g_psum[(g * 4 + 0) * 64 + t] + g_psum[(g * 4 + 1) * 64 + t]
                + g_psum[(g * 4 + 2) * 64 + t] + g_psum[(g * 4 + 3) * 64 + t];
        float m = fmaxf(fmaxf(g_pmax[(g * 4 + 0) * 64 + t], g_pmax[(g * 4 + 1) * 64 + t]),
                        fmaxf(g_pmax[(g * 4 + 2) * 64 + t], g_pmax[(g * 4 + 3) * 64 + t]));
        gv[t] = s / (float)(cnt > 1 ? cnt : 1);
        gv[t + 64] = (cnt > 0) ? m : 0.f;
    }
    __syncthreads();
    float acc = __ldg(bc1 + t);
#pragma unroll 8
    for (int j = 0; j < 128; j++) acc = fmaf(gv[j], Wc1[j * 64 + t], acc);
    float v = lrelu(acc) * __ldg(Wc2 + t);
#pragma unroll
    for (int o = 16; o > 0; o >>= 1) v += __shfl_down_sync(0xffffffffu, v, o);
    __shared__ float part[2];
    if ((t & 31) == 0) part[t >> 5] = v;
    __syncthreads();
    if (t == 0) out[g] = part[0] + part[1] + __ldg(bc2);
}

extern "C" void kernel_launch(void* const* d_in, const int* in_sizes, int n_in,
                              void* d_out, int out_size) {
    const float* x    = (const float*)d_in[0];
    const int*   ei   = (const int*)d_in[1];
    const int*   batch= (const int*)d_in[2];
    const float* W1   = (const float*)d_in[3];
    const float* b1   = (const float*)d_in[4];
    const float* W2   = (const float*)d_in[5];
    const float* b2   = (const float*)d_in[6];
    const float* W3   = (const float*)d_in[7];
    const float* b3   = (const float*)d_in[8];
    const float* W4   = (const float*)d_in[9];
    const float* b4   = (const float*)d_in[10];
    const float* Wc1  = (const float*)d_in[11];
    const float* bc1  = (const float*)d_in[12];
    const float* Wc2  = (const float*)d_in[13];
    const float* bc2  = (const float*)d_in[14];
    float* out = (float*)d_out;

    const int* src = ei;
    const int* dst = ei + NE;

    const int DSM_E = 82944;
    const int DSM_N = 65536;
    cudaFuncSetAttribute(edge_mma_kernel<1>, cudaFuncAttributeMaxDynamicSharedMemorySize, DSM_E);
    cudaFuncSetAttribute(edge_mma_kernel<2>, cudaFuncAttributeMaxDynamicSharedMemorySize, DSM_E);
    cudaFuncSetAttribute(node_mlp64_mma, cudaFuncAttributeMaxDynamicSharedMemorySize, DSM_N);

    const int NB = (NN + 511) / 512;   // 98
    setup_kernel<<<3189, 256>>>(W2, W4, W3);
    hist_kernel<<<(NE + 255) / 256, 256>>>(dst);
    bscan_kernel<<<NB, 512>>>();
    topscan_kernel<<<1, 128>>>(NB);
    scatter_kernel<<<(NE + 255) / 256, 256>>>(src, dst);
    node_mlp6<<<(NN + 127) / 128, 128>>>(x, W1, b1);
    edge_mma_kernel<1><<<NE / 256, 256, DSM_E>>>();
    node_mlp64_mma<<<(NN + 127) / 128, 128, DSM_N>>>(b3, b2);
    edge_mma_kernel<2><<<NE / 256, 256, DSM_E>>>();
    pool_kernel<<<dim3(NG, 4), 256>>>(batch, b4);
    cls_kernel<<<NG, 64>>>(Wc1, bc1, Wc2, bc2, out);
}